// round 6
// baseline (speedup 1.0000x reference)
#include <cuda_runtime.h>
#include <cuda_bf16.h>
#include <cstdint>

// Problem constants
#define BATCH 2
#define SEQN  8192
#define DMODEL 512
#define HEADS 8
#define DK 64
#define KNN 32
#define MROWS (BATCH*SEQN)   // 16384
#define LN_EPS 1e-5f
#define NW (DMODEL*DMODEL)   // 262144
#define NX (MROWS*DMODEL)    // 8388608

// ---------------- scratch (device globals; no allocation allowed) -------------
__device__ __align__(128) float g_Q[NX];
__device__ __align__(128) float g_K[NX];
__device__ __align__(128) float g_V[NX];
__device__ __align__(128) char g_x8h[NX];
__device__ __align__(128) char g_x8l[NX];
__device__ __align__(128) char g_a8h[NX];
__device__ __align__(128) char g_a8l[NX];
__device__ __align__(128) char g_w8h[4 * NW];
__device__ __align__(128) char g_w8l[4 * NW];
__device__ float g_scl[8];   // 0:x 1:Wq 2:Wk 3:Wv 4:Wout 5:V(=att bound)

// ---------------- small helpers -------------------------------------------------
__device__ __forceinline__ uint32_t smem_u32(const void* p) {
    uint32_t a;
    asm("{ .reg .u64 t; cvta.to.shared.u64 t, %1; cvt.u32.u64 %0, t; }"
        : "=r"(a) : "l"(p));
    return a;
}
__device__ __forceinline__ void ldsm_x4(uint32_t (&r)[4], uint32_t addr) {
    asm volatile("ldmatrix.sync.aligned.m8n8.x4.shared.b16 {%0,%1,%2,%3}, [%4];"
                 : "=r"(r[0]), "=r"(r[1]), "=r"(r[2]), "=r"(r[3]) : "r"(addr));
}
__device__ __forceinline__ void imma16832(int (&c)[4], const uint32_t (&a)[4],
                                          const uint32_t b0, const uint32_t b1) {
    asm volatile("mma.sync.aligned.m16n8k32.row.col.s32.s8.s8.s32 "
                 "{%0,%1,%2,%3}, {%4,%5,%6,%7}, {%8,%9}, {%0,%1,%2,%3};"
                 : "+r"(c[0]), "+r"(c[1]), "+r"(c[2]), "+r"(c[3])
                 : "r"(a[0]), "r"(a[1]), "r"(a[2]), "r"(a[3]), "r"(b0), "r"(b1));
}
__device__ __forceinline__ void cp16(uint32_t saddr, const void* gaddr) {
    asm volatile("cp.async.cg.shared.global [%0], [%1], 16;"
                 :: "r"(saddr), "l"(gaddr) : "memory");
}
#define CP_COMMIT() asm volatile("cp.async.commit_group;" ::: "memory")
#define CP_WAIT1()  asm volatile("cp.async.wait_group 1;" ::: "memory")
#define CP_WAIT0()  asm volatile("cp.async.wait_group 0;" ::: "memory")

__device__ __forceinline__ float warp_sum(float v) {
    v += __shfl_xor_sync(0xffffffffu, v, 16);
    v += __shfl_xor_sync(0xffffffffu, v, 8);
    v += __shfl_xor_sync(0xffffffffu, v, 4);
    v += __shfl_xor_sync(0xffffffffu, v, 2);
    v += __shfl_xor_sync(0xffffffffu, v, 1);
    return v;
}
__device__ __forceinline__ float warp_max(float v) {
    v = fmaxf(v, __shfl_xor_sync(0xffffffffu, v, 16));
    v = fmaxf(v, __shfl_xor_sync(0xffffffffu, v, 8));
    v = fmaxf(v, __shfl_xor_sync(0xffffffffu, v, 4));
    v = fmaxf(v, __shfl_xor_sync(0xffffffffu, v, 2));
    v = fmaxf(v, __shfl_xor_sync(0xffffffffu, v, 1));
    return v;
}

// ---------------- scale reset / absmax -----------------------------------------
__global__ void reset_scl() {
    if (threadIdx.x < 8) g_scl[threadIdx.x] = 0.f;
}

__global__ void absmax_k(const float* __restrict__ x, int n4, int si)
{
    const int i = blockIdx.x * blockDim.x + threadIdx.x;
    float m = 0.f;
    if (i < n4) {
        float4 v = ((const float4*)x)[i];
        m = fmaxf(fmaxf(fabsf(v.x), fabsf(v.y)), fmaxf(fabsf(v.z), fabsf(v.w)));
    }
    m = warp_max(m);
    __shared__ float sm[8];
    if ((threadIdx.x & 31) == 0) sm[threadIdx.x >> 5] = m;
    __syncthreads();
    if (threadIdx.x == 0) {
        float b = sm[0];
        #pragma unroll
        for (int w = 1; w < 8; ++w) b = fmaxf(b, sm[w]);
        atomicMax((int*)&g_scl[si], __float_as_int(b));
    }
}

// absmax over the 4 weight matrices in one launch: 256 blocks per matrix
__global__ void absmax_w(const float* __restrict__ w0, const float* __restrict__ w1,
                         const float* __restrict__ w2, const float* __restrict__ w3)
{
    const int seg = blockIdx.x >> 8;
    const float* w = (seg == 0) ? w0 : (seg == 1) ? w1 : (seg == 2) ? w2 : w3;
    const int i = (blockIdx.x & 255) * blockDim.x + threadIdx.x;   // < 65536 float4
    float4 v = ((const float4*)w)[i];
    float m = fmaxf(fmaxf(fabsf(v.x), fabsf(v.y)), fmaxf(fabsf(v.z), fabsf(v.w)));
    m = warp_max(m);
    __shared__ float sm[8];
    if ((threadIdx.x & 31) == 0) sm[threadIdx.x >> 5] = m;
    __syncthreads();
    if (threadIdx.x == 0) {
        float b = sm[0];
        #pragma unroll
        for (int w2_ = 1; w2_ < 8; ++w2_) b = fmaxf(b, sm[w2_]);
        atomicMax((int*)&g_scl[1 + seg], __float_as_int(b));
    }
}

// ---------------- fp32 -> int8 hi/lo split ---------------------------------------
__device__ __forceinline__ void q8(float v, float inv, float step, char& h, char& l) {
    float hf = rintf(v * inv);
    float r  = v - hf * step;
    float lf = rintf(r * 256.f * inv);
    lf = fminf(fmaxf(lf, -127.f), 127.f);
    h = (char)(int)hf;
    l = (char)(int)lf;
}

__global__ void cvt8_k(const float* __restrict__ s, char* __restrict__ hi,
                       char* __restrict__ lo, int si)
{
    const float scl = fmaxf(g_scl[si], 1e-20f);
    const float step = scl * (1.f / 127.f);
    const float inv = 127.f / scl;
    int i = (blockIdx.x * blockDim.x + threadIdx.x) * 4;
    float4 v = *(const float4*)(s + i);
    char h0, h1, h2, h3, l0, l1, l2, l3;
    q8(v.x, inv, step, h0, l0); q8(v.y, inv, step, h1, l1);
    q8(v.z, inv, step, h2, l2); q8(v.w, inv, step, h3, l3);
    *(char4*)(hi + i) = make_char4(h0, h1, h2, h3);
    *(char4*)(lo + i) = make_char4(l0, l1, l2, l3);
}

__global__ void cvt8_w(const float* __restrict__ w0, const float* __restrict__ w1,
                       const float* __restrict__ w2, const float* __restrict__ w3,
                       char* __restrict__ hi, char* __restrict__ lo)
{
    const int seg = blockIdx.x >> 8;
    const float* w = (seg == 0) ? w0 : (seg == 1) ? w1 : (seg == 2) ? w2 : w3;
    const float scl = fmaxf(g_scl[1 + seg], 1e-20f);
    const float step = scl * (1.f / 127.f);
    const float inv = 127.f / scl;
    int i = ((blockIdx.x & 255) * blockDim.x + threadIdx.x) * 4;
    float4 v = *(const float4*)(w + i);
    char h0, h1, h2, h3, l0, l1, l2, l3;
    q8(v.x, inv, step, h0, l0); q8(v.y, inv, step, h1, l1);
    q8(v.z, inv, step, h2, l2); q8(v.w, inv, step, h3, l3);
    *(char4*)(hi + seg * NW + i) = make_char4(h0, h1, h2, h3);
    *(char4*)(lo + seg * NW + i) = make_char4(l0, l1, l2, l3);
}

// ---------------- int8 IMMA GEMM: C_t = A(16384x512) * W_t^T --------------------
// A, W as int8 H/L splits. 3 IMMAs per k32 (hh->acc0, hl+lh->acc1), exact s32.
// C = stepA*stepW*(acc0 + acc1/256). CTA tile 256(M) x 64(N), BKB=64 bytes.
// 8 warps = 4m x 2n, warp tile 64x32. 3-stage cp.async, prefetch 2 ahead.
#define BKB 64
#define NCH8 (DMODEL / BKB)        // 8
#define PITCH8 80                  // bytes per smem row (64 data + 16 pad)
#define TILE_A8 (256 * PITCH8)     // 20480
#define TILE_B8 (64 * PITCH8)      // 5120
#define STAGE8 (2 * TILE_A8 + 2 * TILE_B8)   // 51200
#define NST8 3
#define GEMM_SMEM (NST8 * STAGE8)            // 153600

__global__ __launch_bounds__(256, 1)
void gemm_i8(const char* __restrict__ Ah, const char* __restrict__ Al,
             const char* __restrict__ Wh, const char* __restrict__ Wl,
             float* __restrict__ C0, float* __restrict__ C1, float* __restrict__ C2,
             const float* __restrict__ bias, int a_si, int w_si0)
{
    extern __shared__ char smem[];
    const uint32_t sbase = smem_u32(smem);
    const int tid  = threadIdx.x;
    const int wid  = tid >> 5;
    const int lane = tid & 31;

    const int tmat = blockIdx.x >> 3;              // matrix select
    const int bnn  = (blockIdx.x & 7) * 64;        // col block
    const int bm   = blockIdx.y * 256;
    const int warp_m = wid & 3;                    // 0..3 (64 rows)
    const int warp_n = wid >> 2;                   // 0..1 (32 cols)

    const char* Bh = Wh + (size_t)tmat * NW;
    const char* Bl = Wl + (size_t)tmat * NW;
    float* C = (tmat == 0) ? C0 : (tmat == 1) ? C1 : C2;

    // loader mapping
    const int lrA = tid >> 2;            // 0..63 (A: +p*64), chunk lcA
    const int lc  = tid & 3;             // 16B chunk within 64B row
    const int lrB = tid >> 2;            // 0..63 rows of B

    auto load_stage = [&](int c, int buf) {
        const uint32_t s0 = sbase + buf * STAGE8;
        const int kc = c * BKB;
        #pragma unroll
        for (int t = 0; t < 2; ++t) {
            const char* g = t ? Al : Ah;
            const uint32_t tb = s0 + t * TILE_A8;
            #pragma unroll
            for (int p = 0; p < 4; ++p) {
                const int r = lrA + p * 64;
                cp16(tb + (uint32_t)(r * PITCH8 + lc * 16),
                     g + (size_t)(bm + r) * DMODEL + kc + lc * 16);
            }
        }
        #pragma unroll
        for (int t = 0; t < 2; ++t) {
            const char* g = t ? Bl : Bh;
            const uint32_t tb = s0 + 2 * TILE_A8 + t * TILE_B8;
            cp16(tb + (uint32_t)(lrB * PITCH8 + lc * 16),
                 g + (size_t)(bnn + lrB) * DMODEL + kc + lc * 16);
        }
        CP_COMMIT();
    };

    int acc0[4][4][4], acc1[4][4][4];
    #pragma unroll
    for (int i = 0; i < 4; i++)
        #pragma unroll
        for (int j = 0; j < 4; j++)
            #pragma unroll
            for (int r = 0; r < 4; r++) { acc0[i][j][r] = 0; acc1[i][j][r] = 0; }

    load_stage(0, 0);
    load_stage(1, 1);

    const int aRow  = lane & 15;
    const int aHalf = (lane >> 4) * 16;            // byte offset of col half
    const int quad  = lane >> 3;
    const int bRowL = (quad >> 1) * 8 + (lane & 7);
    const int bHalf = (quad & 1) * 16;

    #pragma unroll 1
    for (int c = 0; c < NCH8; ++c) {
        const int buf = c % NST8;
        if (c + 1 < NCH8) CP_WAIT1(); else CP_WAIT0();
        __syncthreads();
        if (c + 2 < NCH8) load_stage(c + 2, (c + 2) % NST8);

        const uint32_t sAh = sbase + buf * STAGE8;
        const uint32_t sAl = sAh + TILE_A8;
        const uint32_t sBh = sAh + 2 * TILE_A8;
        const uint32_t sBl = sBh + TILE_B8;

        #pragma unroll
        for (int ks = 0; ks < 2; ++ks) {           // two k32 steps per 64B chunk
            uint32_t af[2][4][4];
            uint32_t bfr[2][4][2];
            #pragma unroll
            for (int i = 0; i < 4; ++i) {
                const uint32_t ao = (uint32_t)((warp_m * 64 + i * 16 + aRow) * PITCH8
                                               + ks * 32 + aHalf);
                ldsm_x4(af[0][i], sAh + ao);
                ldsm_x4(af[1][i], sAl + ao);
            }
            #pragma unroll
            for (int p = 0; p < 2; ++p) {
                const uint32_t bo = (uint32_t)((warp_n * 32 + p * 16 + bRowL) * PITCH8
                                               + ks * 32 + bHalf);
                uint32_t r0[4], r1[4];
                ldsm_x4(r0, sBh + bo);
                ldsm_x4(r1, sBl + bo);
                bfr[0][2*p][0]   = r0[0]; bfr[0][2*p][1]   = r0[1];
                bfr[0][2*p+1][0] = r0[2]; bfr[0][2*p+1][1] = r0[3];
                bfr[1][2*p][0]   = r1[0]; bfr[1][2*p][1]   = r1[1];
                bfr[1][2*p+1][0] = r1[2]; bfr[1][2*p+1][1] = r1[3];
            }
            // hh -> acc0
            #pragma unroll
            for (int i = 0; i < 4; ++i)
                #pragma unroll
                for (int j = 0; j < 4; ++j)
                    imma16832(acc0[i][j], af[0][i], bfr[0][j][0], bfr[0][j][1]);
            // hl -> acc1
            #pragma unroll
            for (int i = 0; i < 4; ++i)
                #pragma unroll
                for (int j = 0; j < 4; ++j)
                    imma16832(acc1[i][j], af[0][i], bfr[1][j][0], bfr[1][j][1]);
            // lh -> acc1
            #pragma unroll
            for (int i = 0; i < 4; ++i)
                #pragma unroll
                for (int j = 0; j < 4; ++j)
                    imma16832(acc1[i][j], af[1][i], bfr[0][j][0], bfr[0][j][1]);
        }
    }

    // epilogue: C = F*acc0 + (F/256)*acc1 (+bias)
    const float stepA = fmaxf(g_scl[a_si], 1e-20f) * (1.f / 127.f);
    const float stepW = fmaxf(g_scl[w_si0 + tmat], 1e-20f) * (1.f / 127.f);
    const float F  = stepA * stepW;
    const float F2 = F * (1.f / 256.f);

    const int mBase = bm + warp_m * 64 + (lane >> 2);
    const int nBase = bnn + warp_n * 32 + (lane & 3) * 2;
    #pragma unroll
    for (int i = 0; i < 4; ++i) {
        #pragma unroll
        for (int j = 0; j < 4; ++j) {
            const int row = mBase + i * 16;
            const int col = nBase + j * 8;
            float2 v0, v1;
            v0.x = (float)acc0[i][j][0] * F + (float)acc1[i][j][0] * F2;
            v0.y = (float)acc0[i][j][1] * F + (float)acc1[i][j][1] * F2;
            v1.x = (float)acc0[i][j][2] * F + (float)acc1[i][j][2] * F2;
            v1.y = (float)acc0[i][j][3] * F + (float)acc1[i][j][3] * F2;
            if (bias) {
                const float b0 = bias[col], b1 = bias[col + 1];
                v0.x += b0; v0.y += b1; v1.x += b0; v1.y += b1;
            }
            *(float2*)(C + (size_t)row * DMODEL + col)       = v0;
            *(float2*)(C + (size_t)(row + 8) * DMODEL + col) = v1;
        }
    }
}

// ---------------- LayerNorm over 64-element groups (K only, in place) ----------
__global__ void ln64_kernel(float* __restrict__ Kt)
{
    const int warps_per_block = blockDim.x >> 5;
    int gid = blockIdx.x * warps_per_block + (threadIdx.x >> 5);
    const int lane = threadIdx.x & 31;
    float* base = Kt + (size_t)gid * DK;

    float v0 = base[lane];
    float v1 = base[lane + 32];
    float mean = warp_sum(v0 + v1) * (1.0f / 64.0f);
    float d0 = v0 - mean, d1 = v1 - mean;
    float var = warp_sum(d0 * d0 + d1 * d1) * (1.0f / 64.0f);
    float r = rsqrtf(var + LN_EPS);
    base[lane]      = d0 * r;
    base[lane + 32] = d1 * r;
}

// ---------------- fused gather-attention (Q-LN inline, int8 H/L output) ---------
__global__ __launch_bounds__(256)
void attn_kernel(const float* __restrict__ Q, const float* __restrict__ Kt,
                 const float* __restrict__ V, const int* __restrict__ idx,
                 char* __restrict__ oh, char* __restrict__ ol)
{
    __shared__ int srows[KNN];
    const int bn = blockIdx.x;
    const int b  = bn >> 13;
    const int n  = bn & (SEQN - 1);
    const int tid = threadIdx.x;
    if (tid < KNN) srows[tid] = idx[n * KNN + tid];
    __syncthreads();

    const int h    = tid >> 5;
    const int lane = tid & 31;
    const int qbase = bn * DMODEL + h * DK;
    float q0 = Q[qbase + lane];
    float q1 = Q[qbase + 32 + lane];
    {
        const float mean = warp_sum(q0 + q1) * (1.0f / 64.0f);
        const float d0 = q0 - mean, d1 = q1 - mean;
        const float var = warp_sum(d0 * d0 + d1 * d1) * (1.0f / 64.0f);
        const float r = rsqrtf(var + LN_EPS) * 0.125f;
        q0 = d0 * r; q1 = d1 * r;
    }
    const int rowbase = b * SEQN;

    float s = 0.f;
    #pragma unroll 4
    for (int k = 0; k < KNN; ++k) {
        const int row = srows[k];
        const float* kp = Kt + (size_t)(rowbase + row) * DMODEL + h * DK;
        float p = fmaf(q0, kp[lane], q1 * kp[lane + 32]);
        p += __shfl_xor_sync(0xffffffffu, p, 16);
        p += __shfl_xor_sync(0xffffffffu, p, 8);
        p += __shfl_xor_sync(0xffffffffu, p, 4);
        p += __shfl_xor_sync(0xffffffffu, p, 2);
        p += __shfl_xor_sync(0xffffffffu, p, 1);
        if (lane == k) s = p;
    }

    const float m = warp_max(s);
    const float e = __expf(s - m);
    const float denom = warp_sum(e);
    const float a = e / denom;

    float o0 = 0.f, o1 = 0.f;
    #pragma unroll 4
    for (int k = 0; k < KNN; ++k) {
        const int row = srows[k];
        const float ak = __shfl_sync(0xffffffffu, a, k);
        const float* vp = V + (size_t)(rowbase + row) * DMODEL + h * DK;
        o0 = fmaf(ak, vp[lane],      o0);
        o1 = fmaf(ak, vp[lane + 32], o1);
    }
    // int8 H/L quantization with V's absmax (|o| <= absmax_V, convex combo)
    const float scl = fmaxf(g_scl[5], 1e-20f);
    const float step = scl * (1.f / 127.f);
    const float inv = 127.f / scl;
    char h0, l0, h1, l1;
    q8(o0, inv, step, h0, l0);
    q8(o1, inv, step, h1, l1);
    oh[qbase + lane]      = h0;
    oh[qbase + 32 + lane] = h1;
    ol[qbase + lane]      = l0;
    ol[qbase + 32 + lane] = l1;
}

// ---------------- launch ---------------------------------------------------------
extern "C" void kernel_launch(void* const* d_in, const int* in_sizes, int n_in,
                              void* d_out, int out_size)
{
    const float* x    = (const float*)d_in[0];
    const int*   idx  = (const int*)  d_in[1];
    const float* Wq   = (const float*)d_in[2];
    const float* Wk   = (const float*)d_in[3];
    const float* Wv   = (const float*)d_in[4];
    const float* Wout = (const float*)d_in[5];
    const float* bout = (const float*)d_in[6];
    float* out = (float*)d_out;

    static float *gQ = nullptr, *gK = nullptr, *gV = nullptr;
    static char *xh, *xl, *ah, *al, *wh, *wl;
    if (!gQ) {
        cudaGetSymbolAddress((void**)&gQ, g_Q);
        cudaGetSymbolAddress((void**)&gK, g_K);
        cudaGetSymbolAddress((void**)&gV, g_V);
        cudaGetSymbolAddress((void**)&xh, g_x8h);
        cudaGetSymbolAddress((void**)&xl, g_x8l);
        cudaGetSymbolAddress((void**)&ah, g_a8h);
        cudaGetSymbolAddress((void**)&al, g_a8l);
        cudaGetSymbolAddress((void**)&wh, g_w8h);
        cudaGetSymbolAddress((void**)&wl, g_w8l);
        cudaFuncSetAttribute(gemm_i8, cudaFuncAttributeMaxDynamicSharedMemorySize,
                             GEMM_SMEM);
    }

    // scales (graph-safe: reset every call)
    reset_scl<<<1, 32>>>();
    absmax_k<<<NX / 1024, 256>>>(x, NX / 4, 0);
    absmax_w<<<1024, 256>>>(Wq, Wk, Wv, Wout);

    // int8 H/L conversion
    cvt8_k<<<NX / 1024, 256>>>(x, xh, xl, 0);
    cvt8_w<<<1024, 256>>>(Wq, Wk, Wv, Wout, wh, wl);

    // fused Q,K,V projections: 3 mats x 8 col-blocks x 64 row-blocks
    gemm_i8<<<dim3(24, 64), 256, GEMM_SMEM>>>(xh, xl, wh, wl, gQ, gK, gV,
                                              nullptr, 0, 1);

    // LayerNorm on K (Q's LN fused into attention)
    ln64_kernel<<<(MROWS * HEADS) / 8, 256>>>(gK);

    // V absmax (bounds attention output for its int8 quantization)
    absmax_k<<<NX / 1024, 256>>>(gV, NX / 4, 5);

    attn_kernel<<<MROWS, 256>>>(gQ, gK, gV, idx, ah, al);

    // output projection + bias
    gemm_i8<<<dim3(8, 64), 256, GEMM_SMEM>>>(ah, al, wh + 3 * (size_t)NW,
                                             wl + 3 * (size_t)NW,
                                             out, out, out, bout, 5, 4);
}

// round 7
// speedup vs baseline: 2.3688x; 2.3688x over previous
#include <cuda_runtime.h>
#include <cuda_fp16.h>
#include <cstdint>

// Problem constants
#define BATCH 2
#define SEQN  8192
#define DMODEL 512
#define HEADS 8
#define DK 64
#define KNN 32
#define MROWS (BATCH*SEQN)   // 16384
#define LN_EPS 1e-5f
#define NW (DMODEL*DMODEL)   // 262144
#define NX (MROWS*DMODEL)    // 8388608

// ---------------- scratch (device globals; no allocation allowed) -------------
__device__ __align__(128) float g_Q[NX];
__device__ __align__(128) float g_K[NX];
__device__ __align__(128) float g_V[NX];
__device__ __align__(128) __half g_xh[NX];        // x in fp16 (single)
__device__ __align__(128) __half g_ah[NX];        // attention out in fp16 (single)
__device__ __align__(128) __half g_wh[4 * NW];    // weights fp16 hi
__device__ __align__(128) __half g_wl[4 * NW];    // weights fp16 lo

// ---------------- small helpers -------------------------------------------------
__device__ __forceinline__ uint32_t smem_u32(const void* p) {
    uint32_t a;
    asm("{ .reg .u64 t; cvta.to.shared.u64 t, %1; cvt.u32.u64 %0, t; }"
        : "=r"(a) : "l"(p));
    return a;
}
__device__ __forceinline__ void ldsm_x4(uint32_t (&r)[4], uint32_t addr) {
    asm volatile("ldmatrix.sync.aligned.m8n8.x4.shared.b16 {%0,%1,%2,%3}, [%4];"
                 : "=r"(r[0]), "=r"(r[1]), "=r"(r[2]), "=r"(r[3]) : "r"(addr));
}
__device__ __forceinline__ void mma16816(float (&c)[4], const uint32_t (&a)[4],
                                         const uint32_t b0, const uint32_t b1) {
    asm volatile("mma.sync.aligned.m16n8k16.row.col.f32.f16.f16.f32 "
                 "{%0,%1,%2,%3}, {%4,%5,%6,%7}, {%8,%9}, {%0,%1,%2,%3};"
                 : "+f"(c[0]), "+f"(c[1]), "+f"(c[2]), "+f"(c[3])
                 : "r"(a[0]), "r"(a[1]), "r"(a[2]), "r"(a[3]), "r"(b0), "r"(b1));
}
__device__ __forceinline__ void cp16(uint32_t saddr, const void* gaddr) {
    asm volatile("cp.async.cg.shared.global [%0], [%1], 16;"
                 :: "r"(saddr), "l"(gaddr) : "memory");
}
#define CP_COMMIT() asm volatile("cp.async.commit_group;" ::: "memory")
#define CP_WAIT1()  asm volatile("cp.async.wait_group 1;" ::: "memory")
#define CP_WAIT0()  asm volatile("cp.async.wait_group 0;" ::: "memory")

__device__ __forceinline__ float warp_sum(float v) {
    v += __shfl_xor_sync(0xffffffffu, v, 16);
    v += __shfl_xor_sync(0xffffffffu, v, 8);
    v += __shfl_xor_sync(0xffffffffu, v, 4);
    v += __shfl_xor_sync(0xffffffffu, v, 2);
    v += __shfl_xor_sync(0xffffffffu, v, 1);
    return v;
}
__device__ __forceinline__ float warp_max(float v) {
    v = fmaxf(v, __shfl_xor_sync(0xffffffffu, v, 16));
    v = fmaxf(v, __shfl_xor_sync(0xffffffffu, v, 8));
    v = fmaxf(v, __shfl_xor_sync(0xffffffffu, v, 4));
    v = fmaxf(v, __shfl_xor_sync(0xffffffffu, v, 2));
    v = fmaxf(v, __shfl_xor_sync(0xffffffffu, v, 1));
    return v;
}

// ---------------- GEMM: C_t = A(16384x512,fp16) * (Wh_t + Wl_t)^T ---------------
// A single fp16 operand; W as exact fp16 hi/lo pair. 2 MMAs per k-step.
// CTA tile 256(M) x 128(N), BK=32, 8 warps (4m x 2n), warp tile 64x64.
// 3-stage cp.async pipeline, one sync per chunk, prefetch 2 ahead.
#define BKC 32
#define NCH (DMODEL / BKC)     // 16
#define PITCH 40               // fp16 elems per smem row (80B, conflict-free ldmatrix)
#define TILE_A_B (256 * PITCH * 2)      // 20480 B
#define TILE_B_B (128 * PITCH * 2)      // 10240 B
#define STAGE_B (TILE_A_B + 2 * TILE_B_B)   // 40960 B
#define NSTAGE 3
#define GEMM_SMEM (NSTAGE * STAGE_B)        // 122880 B

__global__ __launch_bounds__(256, 1)
void gemm_f16x2(const __half* __restrict__ A,
                const __half* __restrict__ Wh, const __half* __restrict__ Wl,
                float* __restrict__ C0, float* __restrict__ C1, float* __restrict__ C2,
                const float* __restrict__ bias)
{
    extern __shared__ char smem[];
    const uint32_t sbase = smem_u32(smem);
    const int tid  = threadIdx.x;
    const int wid  = tid >> 5;
    const int lane = tid & 31;

    const int tmat = blockIdx.x >> 2;              // weight matrix / output select
    const int bnn  = (blockIdx.x & 3) * 128;       // col block
    const int bm   = blockIdx.y * 256;
    const int warp_m = wid & 3;                    // 0..3 (64 rows)
    const int warp_n = wid >> 2;                   // 0..1 (64 cols)

    const __half* Bh = Wh + (size_t)tmat * NW;
    const __half* Bl = Wl + (size_t)tmat * NW;
    float* C = (tmat == 0) ? C0 : (tmat == 1) ? C1 : C2;

    const int lr = tid >> 2;             // 0..63
    const int lc = tid & 3;              // 16B chunk

    auto load_stage = [&](int c, int buf) {
        const uint32_t s0 = sbase + buf * STAGE_B;
        const int kc = c * BKC;
        // A tile: 256 rows
        #pragma unroll
        for (int p = 0; p < 4; ++p) {
            const int r = lr + p * 64;
            cp16(s0 + (uint32_t)(r * (PITCH * 2) + lc * 16),
                 A + (size_t)(bm + r) * DMODEL + kc + lc * 8);
        }
        // B tiles (hi, lo): 128 rows each
        #pragma unroll
        for (int t = 0; t < 2; ++t) {
            const __half* g = t ? Bl : Bh;
            const uint32_t tb = s0 + TILE_A_B + t * TILE_B_B;
            #pragma unroll
            for (int p = 0; p < 2; ++p) {
                const int r = lr + p * 64;
                cp16(tb + (uint32_t)(r * (PITCH * 2) + lc * 16),
                     g + (size_t)(bnn + r) * DMODEL + kc + lc * 8);
            }
        }
        CP_COMMIT();
    };

    float acc[4][8][4];
    #pragma unroll
    for (int i = 0; i < 4; i++)
        #pragma unroll
        for (int j = 0; j < 8; j++)
            #pragma unroll
            for (int r = 0; r < 4; r++) acc[i][j][r] = 0.f;

    load_stage(0, 0);
    load_stage(1, 1);

    const int aRow  = lane & 15;
    const int aColB = (lane >> 4) * 8;
    const int quad  = lane >> 3;
    const int bRowL = (quad >> 1) * 8 + (lane & 7);
    const int bColB = (quad & 1) * 8;

    #pragma unroll 1
    for (int c = 0; c < NCH; ++c) {
        const int buf = c % NSTAGE;
        if (c + 1 < NCH) CP_WAIT1(); else CP_WAIT0();
        __syncthreads();
        if (c + 2 < NCH) load_stage(c + 2, (c + 2) % NSTAGE);

        const uint32_t sA  = sbase + buf * STAGE_B;
        const uint32_t sBh = sA + TILE_A_B;
        const uint32_t sBl = sBh + TILE_B_B;

        #pragma unroll
        for (int ks = 0; ks < 2; ++ks) {
            uint32_t af[4][4];
            uint32_t bfr[2][8][2];
            #pragma unroll
            for (int i = 0; i < 4; ++i) {
                const uint32_t ao = (uint32_t)((warp_m * 64 + i * 16 + aRow) * PITCH
                                               + ks * 16 + aColB) * 2;
                ldsm_x4(af[i], sA + ao);
            }
            #pragma unroll
            for (int p = 0; p < 4; ++p) {
                const uint32_t bo = (uint32_t)((warp_n * 64 + p * 16 + bRowL) * PITCH
                                               + ks * 16 + bColB) * 2;
                uint32_t r0[4], r1[4];
                ldsm_x4(r0, sBh + bo);
                ldsm_x4(r1, sBl + bo);
                bfr[0][2*p][0]   = r0[0]; bfr[0][2*p][1]   = r0[1];
                bfr[0][2*p+1][0] = r0[2]; bfr[0][2*p+1][1] = r0[3];
                bfr[1][2*p][0]   = r1[0]; bfr[1][2*p][1]   = r1[1];
                bfr[1][2*p+1][0] = r1[2]; bfr[1][2*p+1][1] = r1[3];
            }
            // 2 terms: A*Wh then A*Wl; 32 independent MMAs between acc reuse
            #pragma unroll
            for (int t = 0; t < 2; ++t)
                #pragma unroll
                for (int i = 0; i < 4; ++i)
                    #pragma unroll
                    for (int j = 0; j < 8; ++j)
                        mma16816(acc[i][j], af[i], bfr[t][j][0], bfr[t][j][1]);
        }
    }

    // epilogue
    const int mBase = bm + warp_m * 64 + (lane >> 2);
    const int nBase = bnn + warp_n * 64 + (lane & 3) * 2;
    #pragma unroll
    for (int i = 0; i < 4; ++i) {
        #pragma unroll
        for (int j = 0; j < 8; ++j) {
            const int row = mBase + i * 16;
            const int col = nBase + j * 8;
            float2 v0 = make_float2(acc[i][j][0], acc[i][j][1]);
            float2 v1 = make_float2(acc[i][j][2], acc[i][j][3]);
            if (bias) {
                const float b0 = bias[col], b1 = bias[col + 1];
                v0.x += b0; v0.y += b1; v1.x += b0; v1.y += b1;
            }
            *(float2*)(C + (size_t)row * DMODEL + col)       = v0;
            *(float2*)(C + (size_t)(row + 8) * DMODEL + col) = v1;
        }
    }
}

// ---------------- fp32 -> fp16 (single) ------------------------------------------
__global__ void cvt_h(const float* __restrict__ s, __half* __restrict__ d)
{
    int i = (blockIdx.x * blockDim.x + threadIdx.x) * 4;
    float4 v = *(const float4*)(s + i);
    __half2* p = (__half2*)(d + i);
    p[0] = __floats2half2_rn(v.x, v.y);
    p[1] = __floats2half2_rn(v.z, v.w);
}

// ---------------- weights fp32 -> fp16 hi/lo -------------------------------------
__global__ void cvt_w(const float* __restrict__ w0, const float* __restrict__ w1,
                      const float* __restrict__ w2, const float* __restrict__ w3,
                      __half* __restrict__ hi, __half* __restrict__ lo)
{
    const int seg = blockIdx.x >> 8;
    const float* w = (seg == 0) ? w0 : (seg == 1) ? w1 : (seg == 2) ? w2 : w3;
    int i = ((blockIdx.x & 255) * blockDim.x + threadIdx.x) * 4;
    float4 v = *(const float4*)(w + i);
    __half h0 = __float2half(v.x), h1 = __float2half(v.y);
    __half h2 = __float2half(v.z), h3 = __float2half(v.w);
    __half l0 = __float2half(v.x - __half2float(h0));
    __half l1 = __float2half(v.y - __half2float(h1));
    __half l2 = __float2half(v.z - __half2float(h2));
    __half l3 = __float2half(v.w - __half2float(h3));
    __half2* hp = (__half2*)(hi + seg * NW + i);
    __half2* lp = (__half2*)(lo + seg * NW + i);
    hp[0] = __halves2half2(h0, h1); hp[1] = __halves2half2(h2, h3);
    lp[0] = __halves2half2(l0, l1); lp[1] = __halves2half2(l2, l3);
}

// ---------------- LayerNorm over 64-element groups (K only, in place) ----------
__global__ void ln64_kernel(float* __restrict__ Kt)
{
    const int warps_per_block = blockDim.x >> 5;
    int gid = blockIdx.x * warps_per_block + (threadIdx.x >> 5);
    const int lane = threadIdx.x & 31;
    float* base = Kt + (size_t)gid * DK;

    float v0 = base[lane];
    float v1 = base[lane + 32];
    float mean = warp_sum(v0 + v1) * (1.0f / 64.0f);
    float d0 = v0 - mean, d1 = v1 - mean;
    float var = warp_sum(d0 * d0 + d1 * d1) * (1.0f / 64.0f);
    float r = rsqrtf(var + LN_EPS);
    base[lane]      = d0 * r;
    base[lane + 32] = d1 * r;
}

// ---------------- fused gather-attention (Q-LN inline, fp16 output) -------------
__global__ __launch_bounds__(256)
void attn_kernel(const float* __restrict__ Q, const float* __restrict__ Kt,
                 const float* __restrict__ V, const int* __restrict__ idx,
                 __half* __restrict__ oh)
{
    __shared__ int srows[KNN];
    const int bn = blockIdx.x;
    const int b  = bn >> 13;
    const int n  = bn & (SEQN - 1);
    const int tid = threadIdx.x;
    if (tid < KNN) srows[tid] = idx[n * KNN + tid];
    __syncthreads();

    const int h    = tid >> 5;
    const int lane = tid & 31;
    const int qbase = bn * DMODEL + h * DK;
    float q0 = Q[qbase + lane];
    float q1 = Q[qbase + 32 + lane];
    // fused LayerNorm(q) and 1/sqrt(dk) scaling
    {
        const float mean = warp_sum(q0 + q1) * (1.0f / 64.0f);
        const float d0 = q0 - mean, d1 = q1 - mean;
        const float var = warp_sum(d0 * d0 + d1 * d1) * (1.0f / 64.0f);
        const float r = rsqrtf(var + LN_EPS) * 0.125f;
        q0 = d0 * r; q1 = d1 * r;
    }
    const int rowbase = b * SEQN;

    float s = 0.f;
    #pragma unroll 4
    for (int k = 0; k < KNN; ++k) {
        const int row = srows[k];
        const float* kp = Kt + (size_t)(rowbase + row) * DMODEL + h * DK;
        float p = fmaf(q0, kp[lane], q1 * kp[lane + 32]);
        p += __shfl_xor_sync(0xffffffffu, p, 16);
        p += __shfl_xor_sync(0xffffffffu, p, 8);
        p += __shfl_xor_sync(0xffffffffu, p, 4);
        p += __shfl_xor_sync(0xffffffffu, p, 2);
        p += __shfl_xor_sync(0xffffffffu, p, 1);
        if (lane == k) s = p;
    }

    const float m = warp_max(s);
    const float e = __expf(s - m);
    const float denom = warp_sum(e);
    const float a = e / denom;

    float o0 = 0.f, o1 = 0.f;
    #pragma unroll 4
    for (int k = 0; k < KNN; ++k) {
        const int row = srows[k];
        const float ak = __shfl_sync(0xffffffffu, a, k);
        const float* vp = V + (size_t)(rowbase + row) * DMODEL + h * DK;
        o0 = fmaf(ak, vp[lane],      o0);
        o1 = fmaf(ak, vp[lane + 32], o1);
    }
    oh[qbase + lane]      = __float2half(o0);
    oh[qbase + 32 + lane] = __float2half(o1);
}

// ---------------- launch ---------------------------------------------------------
extern "C" void kernel_launch(void* const* d_in, const int* in_sizes, int n_in,
                              void* d_out, int out_size)
{
    const float* x    = (const float*)d_in[0];
    const int*   idx  = (const int*)  d_in[1];
    const float* Wq   = (const float*)d_in[2];
    const float* Wk   = (const float*)d_in[3];
    const float* Wv   = (const float*)d_in[4];
    const float* Wout = (const float*)d_in[5];
    const float* bout = (const float*)d_in[6];
    float* out = (float*)d_out;

    static float *gQ = nullptr, *gK = nullptr, *gV = nullptr;
    static __half *xh, *ah, *wh, *wl;
    if (!gQ) {
        cudaGetSymbolAddress((void**)&gQ, g_Q);
        cudaGetSymbolAddress((void**)&gK, g_K);
        cudaGetSymbolAddress((void**)&gV, g_V);
        cudaGetSymbolAddress((void**)&xh, g_xh);
        cudaGetSymbolAddress((void**)&ah, g_ah);
        cudaGetSymbolAddress((void**)&wh, g_wh);
        cudaGetSymbolAddress((void**)&wl, g_wl);
        cudaFuncSetAttribute(gemm_f16x2, cudaFuncAttributeMaxDynamicSharedMemorySize,
                             GEMM_SMEM);
    }

    // conversions
    cvt_h<<<NX / 1024, 256>>>(x, xh);
    cvt_w<<<1024, 256>>>(Wq, Wk, Wv, Wout, wh, wl);

    // fused Q,K,V projections: 3 matrices x 4 col-blocks x 64 row-blocks
    gemm_f16x2<<<dim3(12, 64), 256, GEMM_SMEM>>>(xh, wh, wl, gQ, gK, gV, nullptr);

    // LayerNorm on K only (Q's LN fused into attention)
    ln64_kernel<<<(MROWS * HEADS) / 8, 256>>>(gK);

    attn_kernel<<<MROWS, 256>>>(gQ, gK, gV, idx, ah);

    // output projection + bias
    gemm_f16x2<<<dim3(4, 64), 256, GEMM_SMEM>>>(ah, wh + 3 * (size_t)NW,
                                                wl + 3 * (size_t)NW,
                                                out, out, out, bout);
}

// round 8
// speedup vs baseline: 2.5829x; 1.0904x over previous
#include <cuda_runtime.h>
#include <cuda_fp16.h>
#include <cstdint>

// Problem constants
#define BATCH 2
#define SEQN  8192
#define DMODEL 512
#define HEADS 8
#define DK 64
#define KNN 32
#define MROWS (BATCH*SEQN)   // 16384
#define LN_EPS 1e-5f
#define NW (DMODEL*DMODEL)   // 262144
#define NX (MROWS*DMODEL)    // 8388608

// ---------------- scratch (device globals; no allocation allowed) -------------
__device__ __align__(128) __half g_Q[NX];
__device__ __align__(128) __half g_K[NX];
__device__ __align__(128) __half g_V[NX];
__device__ __align__(128) __half g_xh[NX];        // x in fp16
__device__ __align__(128) __half g_ah[NX];        // attention out in fp16
__device__ __align__(128) __half g_wh[4 * NW];    // weights fp16 hi
__device__ __align__(128) __half g_wl[4 * NW];    // weights fp16 lo

// ---------------- small helpers -------------------------------------------------
__device__ __forceinline__ uint32_t smem_u32(const void* p) {
    uint32_t a;
    asm("{ .reg .u64 t; cvta.to.shared.u64 t, %1; cvt.u32.u64 %0, t; }"
        : "=r"(a) : "l"(p));
    return a;
}
__device__ __forceinline__ void ldsm_x4(uint32_t (&r)[4], uint32_t addr) {
    asm volatile("ldmatrix.sync.aligned.m8n8.x4.shared.b16 {%0,%1,%2,%3}, [%4];"
                 : "=r"(r[0]), "=r"(r[1]), "=r"(r[2]), "=r"(r[3]) : "r"(addr));
}
__device__ __forceinline__ void mma16816(float (&c)[4], const uint32_t (&a)[4],
                                         const uint32_t b0, const uint32_t b1) {
    asm volatile("mma.sync.aligned.m16n8k16.row.col.f32.f16.f16.f32 "
                 "{%0,%1,%2,%3}, {%4,%5,%6,%7}, {%8,%9}, {%0,%1,%2,%3};"
                 : "+f"(c[0]), "+f"(c[1]), "+f"(c[2]), "+f"(c[3])
                 : "r"(a[0]), "r"(a[1]), "r"(a[2]), "r"(a[3]), "r"(b0), "r"(b1));
}
__device__ __forceinline__ void cp16(uint32_t saddr, const void* gaddr) {
    asm volatile("cp.async.cg.shared.global [%0], [%1], 16;"
                 :: "r"(saddr), "l"(gaddr) : "memory");
}
#define CP_COMMIT() asm volatile("cp.async.commit_group;" ::: "memory")
#define CP_WAIT1()  asm volatile("cp.async.wait_group 1;" ::: "memory")
#define CP_WAIT0()  asm volatile("cp.async.wait_group 0;" ::: "memory")

__device__ __forceinline__ float warp_sum(float v) {
    v += __shfl_xor_sync(0xffffffffu, v, 16);
    v += __shfl_xor_sync(0xffffffffu, v, 8);
    v += __shfl_xor_sync(0xffffffffu, v, 4);
    v += __shfl_xor_sync(0xffffffffu, v, 2);
    v += __shfl_xor_sync(0xffffffffu, v, 1);
    return v;
}
__device__ __forceinline__ float warp_max(float v) {
    v = fmaxf(v, __shfl_xor_sync(0xffffffffu, v, 16));
    v = fmaxf(v, __shfl_xor_sync(0xffffffffu, v, 8));
    v = fmaxf(v, __shfl_xor_sync(0xffffffffu, v, 4));
    v = fmaxf(v, __shfl_xor_sync(0xffffffffu, v, 2));
    v = fmaxf(v, __shfl_xor_sync(0xffffffffu, v, 1));
    return v;
}

// ---------------- GEMM: C_t = A(16384x512,fp16) * (Wh_t + Wl_t)^T ---------------
// A single fp16 operand; W as exact fp16 hi/lo pair. 2 MMAs per k-step.
// CTA tile 256(M) x 128(N), BK=32, 8 warps (4m x 2n), warp tile 64x64.
// 3-stage cp.async. OUT_HALF selects fp16 or fp32 output.
#define BKC 32
#define NCH (DMODEL / BKC)     // 16
#define PITCH 40               // fp16 elems per smem row (80B, conflict-free ldmatrix)
#define TILE_A_B (256 * PITCH * 2)      // 20480 B
#define TILE_B_B (128 * PITCH * 2)      // 10240 B
#define STAGE_B (TILE_A_B + 2 * TILE_B_B)   // 40960 B
#define NSTAGE 3
#define GEMM_SMEM (NSTAGE * STAGE_B)        // 122880 B

template <int OUT_HALF>
__global__ __launch_bounds__(256, 1)
void gemm_f16x2(const __half* __restrict__ A,
                const __half* __restrict__ Wh, const __half* __restrict__ Wl,
                void* __restrict__ C0, void* __restrict__ C1, void* __restrict__ C2,
                const float* __restrict__ bias)
{
    extern __shared__ char smem[];
    const uint32_t sbase = smem_u32(smem);
    const int tid  = threadIdx.x;
    const int wid  = tid >> 5;
    const int lane = tid & 31;

    const int tmat = blockIdx.x >> 2;              // weight matrix / output select
    const int bnn  = (blockIdx.x & 3) * 128;       // col block
    const int bm   = blockIdx.y * 256;
    const int warp_m = wid & 3;                    // 0..3 (64 rows)
    const int warp_n = wid >> 2;                   // 0..1 (64 cols)

    const __half* Bh = Wh + (size_t)tmat * NW;
    const __half* Bl = Wl + (size_t)tmat * NW;
    void* C = (tmat == 0) ? C0 : (tmat == 1) ? C1 : C2;

    const int lr = tid >> 2;
    const int lc = tid & 3;

    auto load_stage = [&](int c, int buf) {
        const uint32_t s0 = sbase + buf * STAGE_B;
        const int kc = c * BKC;
        #pragma unroll
        for (int p = 0; p < 4; ++p) {
            const int r = lr + p * 64;
            cp16(s0 + (uint32_t)(r * (PITCH * 2) + lc * 16),
                 A + (size_t)(bm + r) * DMODEL + kc + lc * 8);
        }
        #pragma unroll
        for (int t = 0; t < 2; ++t) {
            const __half* g = t ? Bl : Bh;
            const uint32_t tb = s0 + TILE_A_B + t * TILE_B_B;
            #pragma unroll
            for (int p = 0; p < 2; ++p) {
                const int r = lr + p * 64;
                cp16(tb + (uint32_t)(r * (PITCH * 2) + lc * 16),
                     g + (size_t)(bnn + r) * DMODEL + kc + lc * 8);
            }
        }
        CP_COMMIT();
    };

    float acc[4][8][4];
    #pragma unroll
    for (int i = 0; i < 4; i++)
        #pragma unroll
        for (int j = 0; j < 8; j++)
            #pragma unroll
            for (int r = 0; r < 4; r++) acc[i][j][r] = 0.f;

    load_stage(0, 0);
    load_stage(1, 1);

    const int aRow  = lane & 15;
    const int aColB = (lane >> 4) * 8;
    const int quad  = lane >> 3;
    const int bRowL = (quad >> 1) * 8 + (lane & 7);
    const int bColB = (quad & 1) * 8;

    #pragma unroll 1
    for (int c = 0; c < NCH; ++c) {
        const int buf = c % NSTAGE;
        if (c + 1 < NCH) CP_WAIT1(); else CP_WAIT0();
        __syncthreads();
        if (c + 2 < NCH) load_stage(c + 2, (c + 2) % NSTAGE);

        const uint32_t sA  = sbase + buf * STAGE_B;
        const uint32_t sBh = sA + TILE_A_B;
        const uint32_t sBl = sBh + TILE_B_B;

        #pragma unroll
        for (int ks = 0; ks < 2; ++ks) {
            uint32_t af[4][4];
            uint32_t bfr[2][8][2];
            #pragma unroll
            for (int i = 0; i < 4; ++i) {
                const uint32_t ao = (uint32_t)((warp_m * 64 + i * 16 + aRow) * PITCH
                                               + ks * 16 + aColB) * 2;
                ldsm_x4(af[i], sA + ao);
            }
            #pragma unroll
            for (int p = 0; p < 4; ++p) {
                const uint32_t bo = (uint32_t)((warp_n * 64 + p * 16 + bRowL) * PITCH
                                               + ks * 16 + bColB) * 2;
                uint32_t r0[4], r1[4];
                ldsm_x4(r0, sBh + bo);
                ldsm_x4(r1, sBl + bo);
                bfr[0][2*p][0]   = r0[0]; bfr[0][2*p][1]   = r0[1];
                bfr[0][2*p+1][0] = r0[2]; bfr[0][2*p+1][1] = r0[3];
                bfr[1][2*p][0]   = r1[0]; bfr[1][2*p][1]   = r1[1];
                bfr[1][2*p+1][0] = r1[2]; bfr[1][2*p+1][1] = r1[3];
            }
            #pragma unroll
            for (int t = 0; t < 2; ++t)
                #pragma unroll
                for (int i = 0; i < 4; ++i)
                    #pragma unroll
                    for (int j = 0; j < 8; ++j)
                        mma16816(acc[i][j], af[i], bfr[t][j][0], bfr[t][j][1]);
        }
    }

    // epilogue
    const int mBase = bm + warp_m * 64 + (lane >> 2);
    const int nBase = bnn + warp_n * 64 + (lane & 3) * 2;
    #pragma unroll
    for (int i = 0; i < 4; ++i) {
        #pragma unroll
        for (int j = 0; j < 8; ++j) {
            const int row = mBase + i * 16;
            const int col = nBase + j * 8;
            float2 v0 = make_float2(acc[i][j][0], acc[i][j][1]);
            float2 v1 = make_float2(acc[i][j][2], acc[i][j][3]);
            if (bias) {
                const float b0 = bias[col], b1 = bias[col + 1];
                v0.x += b0; v0.y += b1; v1.x += b0; v1.y += b1;
            }
            if (OUT_HALF) {
                __half* Ch = (__half*)C;
                *(__half2*)(Ch + (size_t)row * DMODEL + col) =
                    __floats2half2_rn(v0.x, v0.y);
                *(__half2*)(Ch + (size_t)(row + 8) * DMODEL + col) =
                    __floats2half2_rn(v1.x, v1.y);
            } else {
                float* Cf = (float*)C;
                *(float2*)(Cf + (size_t)row * DMODEL + col)       = v0;
                *(float2*)(Cf + (size_t)(row + 8) * DMODEL + col) = v1;
            }
        }
    }
}

// ---------------- fp32 -> fp16 (single) ------------------------------------------
__global__ void cvt_h(const float* __restrict__ s, __half* __restrict__ d)
{
    int i = (blockIdx.x * blockDim.x + threadIdx.x) * 4;
    float4 v = *(const float4*)(s + i);
    __half2* p = (__half2*)(d + i);
    p[0] = __floats2half2_rn(v.x, v.y);
    p[1] = __floats2half2_rn(v.z, v.w);
}

// ---------------- weights fp32 -> fp16 hi/lo -------------------------------------
__global__ void cvt_w(const float* __restrict__ w0, const float* __restrict__ w1,
                      const float* __restrict__ w2, const float* __restrict__ w3,
                      __half* __restrict__ hi, __half* __restrict__ lo)
{
    const int seg = blockIdx.x >> 8;
    const float* w = (seg == 0) ? w0 : (seg == 1) ? w1 : (seg == 2) ? w2 : w3;
    int i = ((blockIdx.x & 255) * blockDim.x + threadIdx.x) * 4;
    float4 v = *(const float4*)(w + i);
    __half h0 = __float2half(v.x), h1 = __float2half(v.y);
    __half h2 = __float2half(v.z), h3 = __float2half(v.w);
    __half l0 = __float2half(v.x - __half2float(h0));
    __half l1 = __float2half(v.y - __half2float(h1));
    __half l2 = __float2half(v.z - __half2float(h2));
    __half l3 = __float2half(v.w - __half2float(h3));
    __half2* hp = (__half2*)(hi + seg * NW + i);
    __half2* lp = (__half2*)(lo + seg * NW + i);
    hp[0] = __halves2half2(h0, h1); hp[1] = __halves2half2(h2, h3);
    lp[0] = __halves2half2(l0, l1); lp[1] = __halves2half2(l2, l3);
}

// ---------------- LayerNorm over 64-element groups (K fp16, in place) -----------
__global__ void ln64_kernel(__half* __restrict__ Kt)
{
    const int warps_per_block = blockDim.x >> 5;
    int gid = blockIdx.x * warps_per_block + (threadIdx.x >> 5);
    const int lane = threadIdx.x & 31;
    __half2* base = (__half2*)(Kt + (size_t)gid * DK);

    float2 v = __half22float2(base[lane]);
    float mean = warp_sum(v.x + v.y) * (1.0f / 64.0f);
    float d0 = v.x - mean, d1 = v.y - mean;
    float var = warp_sum(d0 * d0 + d1 * d1) * (1.0f / 64.0f);
    float r = rsqrtf(var + LN_EPS);
    base[lane] = __floats2half2_rn(d0 * r, d1 * r);
}

// ---------------- fused gather-attention (fp16 Q/K/V, Q-LN inline) --------------
__global__ __launch_bounds__(256)
void attn_kernel(const __half* __restrict__ Q, const __half* __restrict__ Kt,
                 const __half* __restrict__ V, const int* __restrict__ idx,
                 __half* __restrict__ oh)
{
    __shared__ int srows[KNN];
    const int bn = blockIdx.x;
    const int b  = bn >> 13;
    const int n  = bn & (SEQN - 1);
    const int tid = threadIdx.x;
    if (tid < KNN) srows[tid] = idx[n * KNN + tid];
    __syncthreads();

    const int h    = tid >> 5;
    const int lane = tid & 31;
    const int qbase = bn * DMODEL + h * DK;
    // lane holds elements {2*lane, 2*lane+1} of the 64-dim head vector
    float2 q = __half22float2(((const __half2*)(Q + qbase))[lane]);
    // fused LayerNorm(q) and 1/sqrt(dk) scaling
    {
        const float mean = warp_sum(q.x + q.y) * (1.0f / 64.0f);
        const float d0 = q.x - mean, d1 = q.y - mean;
        const float var = warp_sum(d0 * d0 + d1 * d1) * (1.0f / 64.0f);
        const float r = rsqrtf(var + LN_EPS) * 0.125f;
        q.x = d0 * r; q.y = d1 * r;
    }
    const int rowbase = b * SEQN;

    float s = 0.f;
    #pragma unroll 4
    for (int k = 0; k < KNN; ++k) {
        const int row = srows[k];
        const __half2* kp = (const __half2*)(Kt + (size_t)(rowbase + row) * DMODEL + h * DK);
        float2 kv = __half22float2(kp[lane]);
        float p = fmaf(q.x, kv.x, q.y * kv.y);
        p += __shfl_xor_sync(0xffffffffu, p, 16);
        p += __shfl_xor_sync(0xffffffffu, p, 8);
        p += __shfl_xor_sync(0xffffffffu, p, 4);
        p += __shfl_xor_sync(0xffffffffu, p, 2);
        p += __shfl_xor_sync(0xffffffffu, p, 1);
        if (lane == k) s = p;
    }

    const float m = warp_max(s);
    const float e = __expf(s - m);
    const float denom = warp_sum(e);
    const float a = e / denom;

    float o0 = 0.f, o1 = 0.f;
    #pragma unroll 4
    for (int k = 0; k < KNN; ++k) {
        const int row = srows[k];
        const float ak = __shfl_sync(0xffffffffu, a, k);
        const __half2* vp = (const __half2*)(V + (size_t)(rowbase + row) * DMODEL + h * DK);
        float2 vv = __half22float2(vp[lane]);
        o0 = fmaf(ak, vv.x, o0);
        o1 = fmaf(ak, vv.y, o1);
    }
    ((__half2*)(oh + qbase))[lane] = __floats2half2_rn(o0, o1);
}

// ---------------- launch ---------------------------------------------------------
extern "C" void kernel_launch(void* const* d_in, const int* in_sizes, int n_in,
                              void* d_out, int out_size)
{
    const float* x    = (const float*)d_in[0];
    const int*   idx  = (const int*)  d_in[1];
    const float* Wq   = (const float*)d_in[2];
    const float* Wk   = (const float*)d_in[3];
    const float* Wv   = (const float*)d_in[4];
    const float* Wout = (const float*)d_in[5];
    const float* bout = (const float*)d_in[6];
    float* out = (float*)d_out;

    static __half *gQ = nullptr, *gK, *gV, *xh, *ah, *wh, *wl;
    if (!gQ) {
        cudaGetSymbolAddress((void**)&gQ, g_Q);
        cudaGetSymbolAddress((void**)&gK, g_K);
        cudaGetSymbolAddress((void**)&gV, g_V);
        cudaGetSymbolAddress((void**)&xh, g_xh);
        cudaGetSymbolAddress((void**)&ah, g_ah);
        cudaGetSymbolAddress((void**)&wh, g_wh);
        cudaGetSymbolAddress((void**)&wl, g_wl);
        cudaFuncSetAttribute(gemm_f16x2<0>, cudaFuncAttributeMaxDynamicSharedMemorySize,
                             GEMM_SMEM);
        cudaFuncSetAttribute(gemm_f16x2<1>, cudaFuncAttributeMaxDynamicSharedMemorySize,
                             GEMM_SMEM);
    }

    // conversions
    cvt_h<<<NX / 1024, 256>>>(x, xh);
    cvt_w<<<1024, 256>>>(Wq, Wk, Wv, Wout, wh, wl);

    // fused Q,K,V projections -> fp16 outputs
    gemm_f16x2<1><<<dim3(12, 64), 256, GEMM_SMEM>>>(xh, wh, wl, gQ, gK, gV, nullptr);

    // LayerNorm on K only (Q's LN fused into attention)
    ln64_kernel<<<(MROWS * HEADS) / 8, 256>>>(gK);

    attn_kernel<<<MROWS, 256>>>(gQ, gK, gV, idx, ah);

    // output projection + bias -> fp32 d_out
    gemm_f16x2<0><<<dim3(4, 64), 256, GEMM_SMEM>>>(ah, wh + 3 * (size_t)NW,
                                                   wl + 3 * (size_t)NW,
                                                   out, out, out, bout);
}

// round 9
// speedup vs baseline: 2.7315x; 1.0575x over previous
#include <cuda_runtime.h>
#include <cuda_fp16.h>
#include <cstdint>

// Problem constants
#define BATCH 2
#define SEQN  8192
#define DMODEL 512
#define HEADS 8
#define DK 64
#define KNN 32
#define MROWS (BATCH*SEQN)   // 16384
#define LN_EPS 1e-5f
#define NW (DMODEL*DMODEL)   // 262144
#define NX (MROWS*DMODEL)    // 8388608

// ---------------- scratch (device globals; no allocation allowed) -------------
__device__ __align__(128) __half g_Q[NX];
__device__ __align__(128) __half g_K[NX];
__device__ __align__(128) __half g_V[NX];
__device__ __align__(128) __half g_xh[NX];        // x in fp16
__device__ __align__(128) __half g_ah[NX];        // attention out in fp16
__device__ __align__(128) __half g_wh[4 * NW];    // weights fp16 hi
__device__ __align__(128) __half g_wl[4 * NW];    // weights fp16 lo

// ---------------- small helpers -------------------------------------------------
__device__ __forceinline__ uint32_t smem_u32(const void* p) {
    uint32_t a;
    asm("{ .reg .u64 t; cvta.to.shared.u64 t, %1; cvt.u32.u64 %0, t; }"
        : "=r"(a) : "l"(p));
    return a;
}
__device__ __forceinline__ void ldsm_x4(uint32_t (&r)[4], uint32_t addr) {
    asm volatile("ldmatrix.sync.aligned.m8n8.x4.shared.b16 {%0,%1,%2,%3}, [%4];"
                 : "=r"(r[0]), "=r"(r[1]), "=r"(r[2]), "=r"(r[3]) : "r"(addr));
}
__device__ __forceinline__ void mma16816(float (&c)[4], const uint32_t (&a)[4],
                                         const uint32_t b0, const uint32_t b1) {
    asm volatile("mma.sync.aligned.m16n8k16.row.col.f32.f16.f16.f32 "
                 "{%0,%1,%2,%3}, {%4,%5,%6,%7}, {%8,%9}, {%0,%1,%2,%3};"
                 : "+f"(c[0]), "+f"(c[1]), "+f"(c[2]), "+f"(c[3])
                 : "r"(a[0]), "r"(a[1]), "r"(a[2]), "r"(a[3]), "r"(b0), "r"(b1));
}
__device__ __forceinline__ void cp16(uint32_t saddr, const void* gaddr) {
    asm volatile("cp.async.cg.shared.global [%0], [%1], 16;"
                 :: "r"(saddr), "l"(gaddr) : "memory");
}
#define CP_COMMIT() asm volatile("cp.async.commit_group;" ::: "memory")
#define CP_WAIT1()  asm volatile("cp.async.wait_group 1;" ::: "memory")
#define CP_WAIT0()  asm volatile("cp.async.wait_group 0;" ::: "memory")

__device__ __forceinline__ float warp_sum(float v) {
    v += __shfl_xor_sync(0xffffffffu, v, 16);
    v += __shfl_xor_sync(0xffffffffu, v, 8);
    v += __shfl_xor_sync(0xffffffffu, v, 4);
    v += __shfl_xor_sync(0xffffffffu, v, 2);
    v += __shfl_xor_sync(0xffffffffu, v, 1);
    return v;
}
__device__ __forceinline__ float warp_max(float v) {
    v = fmaxf(v, __shfl_xor_sync(0xffffffffu, v, 16));
    v = fmaxf(v, __shfl_xor_sync(0xffffffffu, v, 8));
    v = fmaxf(v, __shfl_xor_sync(0xffffffffu, v, 4));
    v = fmaxf(v, __shfl_xor_sync(0xffffffffu, v, 2));
    v = fmaxf(v, __shfl_xor_sync(0xffffffffu, v, 1));
    return v;
}

// ---------------- GEMM: C_t = A(16384x512,fp16) * (Wh_t + Wl_t)^T ---------------
// A single fp16 operand; W as exact fp16 hi/lo pair. 2 MMAs per k-step.
// CTA tile 256(M) x 128(N), BK=32, 8 warps (4m x 2n), warp tile 64x64.
// 3-stage cp.async. OUT_HALF: fp16 vs fp32 output. DO_LN: fused per-64-col
// LayerNorm on tmat 0 (with 1/8 scale) and tmat 1 in the epilogue.
#define BKC 32
#define NCH (DMODEL / BKC)     // 16
#define PITCH 40               // fp16 elems per smem row (80B, conflict-free ldmatrix)
#define TILE_A_B (256 * PITCH * 2)      // 20480 B
#define TILE_B_B (128 * PITCH * 2)      // 10240 B
#define STAGE_B (TILE_A_B + 2 * TILE_B_B)   // 40960 B
#define NSTAGE 3
#define GEMM_SMEM (NSTAGE * STAGE_B)        // 122880 B

template <int OUT_HALF, int DO_LN>
__global__ __launch_bounds__(256, 1)
void gemm_f16x2(const __half* __restrict__ A,
                const __half* __restrict__ Wh, const __half* __restrict__ Wl,
                void* __restrict__ C0, void* __restrict__ C1, void* __restrict__ C2,
                const float* __restrict__ bias)
{
    extern __shared__ char smem[];
    const uint32_t sbase = smem_u32(smem);
    const int tid  = threadIdx.x;
    const int wid  = tid >> 5;
    const int lane = tid & 31;

    const int tmat = blockIdx.x >> 2;
    const int bnn  = (blockIdx.x & 3) * 128;
    const int bm   = blockIdx.y * 256;
    const int warp_m = wid & 3;
    const int warp_n = wid >> 2;

    const __half* Bh = Wh + (size_t)tmat * NW;
    const __half* Bl = Wl + (size_t)tmat * NW;
    void* C = (tmat == 0) ? C0 : (tmat == 1) ? C1 : C2;

    const int lr = tid >> 2;
    const int lc = tid & 3;

    auto load_stage = [&](int c, int buf) {
        const uint32_t s0 = sbase + buf * STAGE_B;
        const int kc = c * BKC;
        #pragma unroll
        for (int p = 0; p < 4; ++p) {
            const int r = lr + p * 64;
            cp16(s0 + (uint32_t)(r * (PITCH * 2) + lc * 16),
                 A + (size_t)(bm + r) * DMODEL + kc + lc * 8);
        }
        #pragma unroll
        for (int t = 0; t < 2; ++t) {
            const __half* g = t ? Bl : Bh;
            const uint32_t tb = s0 + TILE_A_B + t * TILE_B_B;
            #pragma unroll
            for (int p = 0; p < 2; ++p) {
                const int r = lr + p * 64;
                cp16(tb + (uint32_t)(r * (PITCH * 2) + lc * 16),
                     g + (size_t)(bnn + r) * DMODEL + kc + lc * 8);
            }
        }
        CP_COMMIT();
    };

    float acc[4][8][4];
    #pragma unroll
    for (int i = 0; i < 4; i++)
        #pragma unroll
        for (int j = 0; j < 8; j++)
            #pragma unroll
            for (int r = 0; r < 4; r++) acc[i][j][r] = 0.f;

    load_stage(0, 0);
    load_stage(1, 1);

    const int aRow  = lane & 15;
    const int aColB = (lane >> 4) * 8;
    const int quad  = lane >> 3;
    const int bRowL = (quad >> 1) * 8 + (lane & 7);
    const int bColB = (quad & 1) * 8;

    #pragma unroll 1
    for (int c = 0; c < NCH; ++c) {
        const int buf = c % NSTAGE;
        if (c + 1 < NCH) CP_WAIT1(); else CP_WAIT0();
        __syncthreads();
        if (c + 2 < NCH) load_stage(c + 2, (c + 2) % NSTAGE);

        const uint32_t sA  = sbase + buf * STAGE_B;
        const uint32_t sBh = sA + TILE_A_B;
        const uint32_t sBl = sBh + TILE_B_B;

        #pragma unroll
        for (int ks = 0; ks < 2; ++ks) {
            uint32_t af[4][4];
            uint32_t bfr[2][8][2];
            #pragma unroll
            for (int i = 0; i < 4; ++i) {
                const uint32_t ao = (uint32_t)((warp_m * 64 + i * 16 + aRow) * PITCH
                                               + ks * 16 + aColB) * 2;
                ldsm_x4(af[i], sA + ao);
            }
            #pragma unroll
            for (int p = 0; p < 4; ++p) {
                const uint32_t bo = (uint32_t)((warp_n * 64 + p * 16 + bRowL) * PITCH
                                               + ks * 16 + bColB) * 2;
                uint32_t r0[4], r1[4];
                ldsm_x4(r0, sBh + bo);
                ldsm_x4(r1, sBl + bo);
                bfr[0][2*p][0]   = r0[0]; bfr[0][2*p][1]   = r0[1];
                bfr[0][2*p+1][0] = r0[2]; bfr[0][2*p+1][1] = r0[3];
                bfr[1][2*p][0]   = r1[0]; bfr[1][2*p][1]   = r1[1];
                bfr[1][2*p+1][0] = r1[2]; bfr[1][2*p+1][1] = r1[3];
            }
            #pragma unroll
            for (int t = 0; t < 2; ++t)
                #pragma unroll
                for (int i = 0; i < 4; ++i)
                    #pragma unroll
                    for (int j = 0; j < 8; ++j)
                        mma16816(acc[i][j], af[i], bfr[t][j][0], bfr[t][j][1]);
        }
    }

    // fused LayerNorm over the 64-col head group (warp tile N == head group).
    // 4 threads of a lane-quad hold all 64 cols of each row; reduce via 2 shfls.
    if (DO_LN && tmat <= 1) {
        const float qscale = (tmat == 0) ? 0.125f : 1.0f;
        #pragma unroll
        for (int i = 0; i < 4; ++i) {
            #pragma unroll
            for (int hf = 0; hf < 2; ++hf) {
                float s = 0.f, s2 = 0.f;
                #pragma unroll
                for (int j = 0; j < 8; ++j) {
                    const float c0 = acc[i][j][hf * 2], c1 = acc[i][j][hf * 2 + 1];
                    s += c0 + c1;
                    s2 += c0 * c0 + c1 * c1;
                }
                s  += __shfl_xor_sync(0xffffffffu, s, 1);
                s  += __shfl_xor_sync(0xffffffffu, s, 2);
                s2 += __shfl_xor_sync(0xffffffffu, s2, 1);
                s2 += __shfl_xor_sync(0xffffffffu, s2, 2);
                const float mean = s * (1.f / 64.f);
                const float var  = s2 * (1.f / 64.f) - mean * mean;
                const float rr   = rsqrtf(var + LN_EPS) * qscale;
                #pragma unroll
                for (int j = 0; j < 8; ++j) {
                    acc[i][j][hf * 2]     = (acc[i][j][hf * 2]     - mean) * rr;
                    acc[i][j][hf * 2 + 1] = (acc[i][j][hf * 2 + 1] - mean) * rr;
                }
            }
        }
    }

    // epilogue
    const int mBase = bm + warp_m * 64 + (lane >> 2);
    const int nBase = bnn + warp_n * 64 + (lane & 3) * 2;
    #pragma unroll
    for (int i = 0; i < 4; ++i) {
        #pragma unroll
        for (int j = 0; j < 8; ++j) {
            const int row = mBase + i * 16;
            const int col = nBase + j * 8;
            float2 v0 = make_float2(acc[i][j][0], acc[i][j][1]);
            float2 v1 = make_float2(acc[i][j][2], acc[i][j][3]);
            if (bias) {
                const float b0 = bias[col], b1 = bias[col + 1];
                v0.x += b0; v0.y += b1; v1.x += b0; v1.y += b1;
            }
            if (OUT_HALF) {
                __half* Ch = (__half*)C;
                *(__half2*)(Ch + (size_t)row * DMODEL + col) =
                    __floats2half2_rn(v0.x, v0.y);
                *(__half2*)(Ch + (size_t)(row + 8) * DMODEL + col) =
                    __floats2half2_rn(v1.x, v1.y);
            } else {
                float* Cf = (float*)C;
                *(float2*)(Cf + (size_t)row * DMODEL + col)       = v0;
                *(float2*)(Cf + (size_t)(row + 8) * DMODEL + col) = v1;
            }
        }
    }
}

// ---------------- fp32 -> fp16 (single) ------------------------------------------
__global__ void cvt_h(const float* __restrict__ s, __half* __restrict__ d)
{
    int i = (blockIdx.x * blockDim.x + threadIdx.x) * 4;
    float4 v = *(const float4*)(s + i);
    __half2* p = (__half2*)(d + i);
    p[0] = __floats2half2_rn(v.x, v.y);
    p[1] = __floats2half2_rn(v.z, v.w);
}

// ---------------- weights fp32 -> fp16 hi/lo -------------------------------------
__global__ void cvt_w(const float* __restrict__ w0, const float* __restrict__ w1,
                      const float* __restrict__ w2, const float* __restrict__ w3,
                      __half* __restrict__ hi, __half* __restrict__ lo)
{
    const int seg = blockIdx.x >> 8;
    const float* w = (seg == 0) ? w0 : (seg == 1) ? w1 : (seg == 2) ? w2 : w3;
    int i = ((blockIdx.x & 255) * blockDim.x + threadIdx.x) * 4;
    float4 v = *(const float4*)(w + i);
    __half h0 = __float2half(v.x), h1 = __float2half(v.y);
    __half h2 = __float2half(v.z), h3 = __float2half(v.w);
    __half l0 = __float2half(v.x - __half2float(h0));
    __half l1 = __float2half(v.y - __half2float(h1));
    __half l2 = __float2half(v.z - __half2float(h2));
    __half l3 = __float2half(v.w - __half2float(h3));
    __half2* hp = (__half2*)(hi + seg * NW + i);
    __half2* lp = (__half2*)(lo + seg * NW + i);
    hp[0] = __halves2half2(h0, h1); hp[1] = __halves2half2(h2, h3);
    lp[0] = __halves2half2(l0, l1); lp[1] = __halves2half2(l2, l3);
}

// ---------------- smem-staged gather-attention (fp16, pre-normalized Q/K) -------
// Per block: stage 32 K rows + 32 V rows (64 KB) via cp.async, then compute.
#define ATT_SMEM 65536

__global__ __launch_bounds__(256)
void attn_kernel(const __half* __restrict__ Q, const __half* __restrict__ Kt,
                 const __half* __restrict__ V, const int* __restrict__ idx,
                 __half* __restrict__ oh)
{
    extern __shared__ char sm[];
    const uint32_t sbase = smem_u32(sm);
    const int bn = blockIdx.x;
    const int b  = bn >> 13;
    const int n  = bn & (SEQN - 1);
    const int tid = threadIdx.x;
    const int rowbase = b * SEQN;
    const int ibase = n * KNN;

    // stage K then V: 32 rows x 1024 B each; 256 threads x 16B, 8 passes/tensor
    const int lrow = tid >> 6;       // 0..3
    const int lchk = tid & 63;       // 16B chunk in row
    #pragma unroll
    for (int p = 0; p < 8; ++p) {
        const int r = p * 4 + lrow;
        const int row = idx[ibase + r];
        cp16(sbase + (uint32_t)(r * 1024 + lchk * 16),
             Kt + ((size_t)(rowbase + row) << 9) + lchk * 8);
    }
    CP_COMMIT();
    #pragma unroll
    for (int p = 0; p < 8; ++p) {
        const int r = p * 4 + lrow;
        const int row = idx[ibase + r];
        cp16(sbase + (uint32_t)(32768 + r * 1024 + lchk * 16),
             V + ((size_t)(rowbase + row) << 9) + lchk * 8);
    }
    CP_COMMIT();

    const int h    = tid >> 5;
    const int lane = tid & 31;
    const int qbase = bn * DMODEL + h * DK;
    // Q already LayerNorm'd and pre-scaled by 1/8 in the GEMM epilogue
    const float2 q = __half22float2(((const __half2*)(Q + qbase))[lane]);

    CP_WAIT1();
    __syncthreads();

    // scores from smem K (broadcast row, conflict-free)
    float s = 0.f;
    #pragma unroll
    for (int k = 0; k < KNN; ++k) {
        const float2 kv = __half22float2(
            *(const __half2*)(sm + k * 1024 + h * 128 + lane * 4));
        float p = fmaf(q.x, kv.x, q.y * kv.y);
        p += __shfl_xor_sync(0xffffffffu, p, 16);
        p += __shfl_xor_sync(0xffffffffu, p, 8);
        p += __shfl_xor_sync(0xffffffffu, p, 4);
        p += __shfl_xor_sync(0xffffffffu, p, 2);
        p += __shfl_xor_sync(0xffffffffu, p, 1);
        if (lane == k) s = p;
    }

    const float m = warp_max(s);
    const float e = __expf(s - m);
    const float denom = warp_sum(e);
    const float a = e / denom;

    CP_WAIT0();
    __syncthreads();

    // output from smem V
    float o0 = 0.f, o1 = 0.f;
    #pragma unroll
    for (int k = 0; k < KNN; ++k) {
        const float ak = __shfl_sync(0xffffffffu, a, k);
        const float2 vv = __half22float2(
            *(const __half2*)(sm + 32768 + k * 1024 + h * 128 + lane * 4));
        o0 = fmaf(ak, vv.x, o0);
        o1 = fmaf(ak, vv.y, o1);
    }
    ((__half2*)(oh + qbase))[lane] = __floats2half2_rn(o0, o1);
}

// ---------------- launch ---------------------------------------------------------
extern "C" void kernel_launch(void* const* d_in, const int* in_sizes, int n_in,
                              void* d_out, int out_size)
{
    const float* x    = (const float*)d_in[0];
    const int*   idx  = (const int*)  d_in[1];
    const float* Wq   = (const float*)d_in[2];
    const float* Wk   = (const float*)d_in[3];
    const float* Wv   = (const float*)d_in[4];
    const float* Wout = (const float*)d_in[5];
    const float* bout = (const float*)d_in[6];
    float* out = (float*)d_out;

    static __half *gQ = nullptr, *gK, *gV, *xh, *ah, *wh, *wl;
    if (!gQ) {
        cudaGetSymbolAddress((void**)&gQ, g_Q);
        cudaGetSymbolAddress((void**)&gK, g_K);
        cudaGetSymbolAddress((void**)&gV, g_V);
        cudaGetSymbolAddress((void**)&xh, g_xh);
        cudaGetSymbolAddress((void**)&ah, g_ah);
        cudaGetSymbolAddress((void**)&wh, g_wh);
        cudaGetSymbolAddress((void**)&wl, g_wl);
        cudaFuncSetAttribute((const void*)gemm_f16x2<1, 1>,
                             cudaFuncAttributeMaxDynamicSharedMemorySize, GEMM_SMEM);
        cudaFuncSetAttribute((const void*)gemm_f16x2<0, 0>,
                             cudaFuncAttributeMaxDynamicSharedMemorySize, GEMM_SMEM);
        cudaFuncSetAttribute((const void*)attn_kernel,
                             cudaFuncAttributeMaxDynamicSharedMemorySize, ATT_SMEM);
    }

    // conversions
    cvt_h<<<NX / 1024, 256>>>(x, xh);
    cvt_w<<<1024, 256>>>(Wq, Wk, Wv, Wout, wh, wl);

    // fused Q,K,V projections -> fp16 outputs; LN fused for Q (x1/8) and K
    gemm_f16x2<1, 1><<<dim3(12, 64), 256, GEMM_SMEM>>>(xh, wh, wl, gQ, gK, gV,
                                                       nullptr);

    // smem-staged attention
    attn_kernel<<<MROWS, 256, ATT_SMEM>>>(gQ, gK, gV, idx, ah);

    // output projection + bias -> fp32 d_out
    gemm_f16x2<0, 0><<<dim3(4, 64), 256, GEMM_SMEM>>>(ah, wh + 3 * (size_t)NW,
                                                      wl + 3 * (size_t)NW,
                                                      out, out, out, bout);
}

// round 10
// speedup vs baseline: 2.9754x; 1.0893x over previous
#include <cuda_runtime.h>
#include <cuda_fp16.h>
#include <cstdint>

// Problem constants
#define BATCH 2
#define SEQN  8192
#define DMODEL 512
#define HEADS 8
#define DK 64
#define KNN 32
#define MROWS (BATCH*SEQN)   // 16384
#define LN_EPS 1e-5f
#define NW (DMODEL*DMODEL)   // 262144
#define NX (MROWS*DMODEL)    // 8388608

// ---------------- scratch (device globals; no allocation allowed) -------------
__device__ __align__(128) __half g_Q[NX];
__device__ __align__(128) __half g_K[NX];
__device__ __align__(128) __half g_V[NX];
__device__ __align__(128) __half g_xh[NX];        // x in fp16
__device__ __align__(128) __half g_ah[NX];        // attention out in fp16
__device__ __align__(128) __half g_wh[4 * NW];    // weights fp16 hi
__device__ __align__(128) __half g_wl[4 * NW];    // weights fp16 lo

// ---------------- small helpers -------------------------------------------------
__device__ __forceinline__ uint32_t smem_u32(const void* p) {
    uint32_t a;
    asm("{ .reg .u64 t; cvta.to.shared.u64 t, %1; cvt.u32.u64 %0, t; }"
        : "=r"(a) : "l"(p));
    return a;
}
__device__ __forceinline__ void ldsm_x4(uint32_t (&r)[4], uint32_t addr) {
    asm volatile("ldmatrix.sync.aligned.m8n8.x4.shared.b16 {%0,%1,%2,%3}, [%4];"
                 : "=r"(r[0]), "=r"(r[1]), "=r"(r[2]), "=r"(r[3]) : "r"(addr));
}
__device__ __forceinline__ void mma16816(float (&c)[4], const uint32_t (&a)[4],
                                         const uint32_t b0, const uint32_t b1) {
    asm volatile("mma.sync.aligned.m16n8k16.row.col.f32.f16.f16.f32 "
                 "{%0,%1,%2,%3}, {%4,%5,%6,%7}, {%8,%9}, {%0,%1,%2,%3};"
                 : "+f"(c[0]), "+f"(c[1]), "+f"(c[2]), "+f"(c[3])
                 : "r"(a[0]), "r"(a[1]), "r"(a[2]), "r"(a[3]), "r"(b0), "r"(b1));
}
__device__ __forceinline__ void cp16(uint32_t saddr, const void* gaddr) {
    asm volatile("cp.async.cg.shared.global [%0], [%1], 16;"
                 :: "r"(saddr), "l"(gaddr) : "memory");
}
#define CP_COMMIT() asm volatile("cp.async.commit_group;" ::: "memory")
#define CP_WAIT1()  asm volatile("cp.async.wait_group 1;" ::: "memory")
#define CP_WAIT0()  asm volatile("cp.async.wait_group 0;" ::: "memory")

__device__ __forceinline__ float warp_sum(float v) {
    v += __shfl_xor_sync(0xffffffffu, v, 16);
    v += __shfl_xor_sync(0xffffffffu, v, 8);
    v += __shfl_xor_sync(0xffffffffu, v, 4);
    v += __shfl_xor_sync(0xffffffffu, v, 2);
    v += __shfl_xor_sync(0xffffffffu, v, 1);
    return v;
}
__device__ __forceinline__ float warp_max(float v) {
    v = fmaxf(v, __shfl_xor_sync(0xffffffffu, v, 16));
    v = fmaxf(v, __shfl_xor_sync(0xffffffffu, v, 8));
    v = fmaxf(v, __shfl_xor_sync(0xffffffffu, v, 4));
    v = fmaxf(v, __shfl_xor_sync(0xffffffffu, v, 2));
    v = fmaxf(v, __shfl_xor_sync(0xffffffffu, v, 1));
    return v;
}

// ---------------- GEMM: C_t = A(16384x512,fp16) * (Wh_t + Wl_t)^T ---------------
// A single fp16 operand; W as exact fp16 hi/lo pair. 2 MMAs per k-step.
// CTA tile 256(M) x 128(N), BK=32, 8 warps (4m x 2n), warp tile 64x64.
// 3-stage cp.async. OUT_HALF: fp16 vs fp32 output. DO_LN: fused per-64-col
// LayerNorm on tmat 0 (with 1/8 scale) and tmat 1 in the epilogue.
#define BKC 32
#define NCH (DMODEL / BKC)     // 16
#define PITCH 40               // fp16 elems per smem row (80B, conflict-free ldmatrix)
#define TILE_A_B (256 * PITCH * 2)      // 20480 B
#define TILE_B_B (128 * PITCH * 2)      // 10240 B
#define STAGE_B (TILE_A_B + 2 * TILE_B_B)   // 40960 B
#define NSTAGE 3
#define GEMM_SMEM (NSTAGE * STAGE_B)        // 122880 B

template <int OUT_HALF, int DO_LN>
__global__ __launch_bounds__(256, 1)
void gemm_f16x2(const __half* __restrict__ A,
                const __half* __restrict__ Wh, const __half* __restrict__ Wl,
                void* __restrict__ C0, void* __restrict__ C1, void* __restrict__ C2,
                const float* __restrict__ bias)
{
    extern __shared__ char smem[];
    const uint32_t sbase = smem_u32(smem);
    const int tid  = threadIdx.x;
    const int wid  = tid >> 5;
    const int lane = tid & 31;

    const int tmat = blockIdx.x >> 2;
    const int bnn  = (blockIdx.x & 3) * 128;
    const int bm   = blockIdx.y * 256;
    const int warp_m = wid & 3;
    const int warp_n = wid >> 2;

    const __half* Bh = Wh + (size_t)tmat * NW;
    const __half* Bl = Wl + (size_t)tmat * NW;
    void* C = (tmat == 0) ? C0 : (tmat == 1) ? C1 : C2;

    const int lr = tid >> 2;
    const int lc = tid & 3;

    auto load_stage = [&](int c, int buf) {
        const uint32_t s0 = sbase + buf * STAGE_B;
        const int kc = c * BKC;
        #pragma unroll
        for (int p = 0; p < 4; ++p) {
            const int r = lr + p * 64;
            cp16(s0 + (uint32_t)(r * (PITCH * 2) + lc * 16),
                 A + (size_t)(bm + r) * DMODEL + kc + lc * 8);
        }
        #pragma unroll
        for (int t = 0; t < 2; ++t) {
            const __half* g = t ? Bl : Bh;
            const uint32_t tb = s0 + TILE_A_B + t * TILE_B_B;
            #pragma unroll
            for (int p = 0; p < 2; ++p) {
                const int r = lr + p * 64;
                cp16(tb + (uint32_t)(r * (PITCH * 2) + lc * 16),
                     g + (size_t)(bnn + r) * DMODEL + kc + lc * 8);
            }
        }
        CP_COMMIT();
    };

    float acc[4][8][4];
    #pragma unroll
    for (int i = 0; i < 4; i++)
        #pragma unroll
        for (int j = 0; j < 8; j++)
            #pragma unroll
            for (int r = 0; r < 4; r++) acc[i][j][r] = 0.f;

    load_stage(0, 0);
    load_stage(1, 1);

    const int aRow  = lane & 15;
    const int aColB = (lane >> 4) * 8;
    const int quad  = lane >> 3;
    const int bRowL = (quad >> 1) * 8 + (lane & 7);
    const int bColB = (quad & 1) * 8;

    #pragma unroll 1
    for (int c = 0; c < NCH; ++c) {
        const int buf = c % NSTAGE;
        if (c + 1 < NCH) CP_WAIT1(); else CP_WAIT0();
        __syncthreads();
        if (c + 2 < NCH) load_stage(c + 2, (c + 2) % NSTAGE);

        const uint32_t sA  = sbase + buf * STAGE_B;
        const uint32_t sBh = sA + TILE_A_B;
        const uint32_t sBl = sBh + TILE_B_B;

        #pragma unroll
        for (int ks = 0; ks < 2; ++ks) {
            uint32_t af[4][4];
            uint32_t bfr[2][8][2];
            #pragma unroll
            for (int i = 0; i < 4; ++i) {
                const uint32_t ao = (uint32_t)((warp_m * 64 + i * 16 + aRow) * PITCH
                                               + ks * 16 + aColB) * 2;
                ldsm_x4(af[i], sA + ao);
            }
            #pragma unroll
            for (int p = 0; p < 4; ++p) {
                const uint32_t bo = (uint32_t)((warp_n * 64 + p * 16 + bRowL) * PITCH
                                               + ks * 16 + bColB) * 2;
                uint32_t r0[4], r1[4];
                ldsm_x4(r0, sBh + bo);
                ldsm_x4(r1, sBl + bo);
                bfr[0][2*p][0]   = r0[0]; bfr[0][2*p][1]   = r0[1];
                bfr[0][2*p+1][0] = r0[2]; bfr[0][2*p+1][1] = r0[3];
                bfr[1][2*p][0]   = r1[0]; bfr[1][2*p][1]   = r1[1];
                bfr[1][2*p+1][0] = r1[2]; bfr[1][2*p+1][1] = r1[3];
            }
            #pragma unroll
            for (int t = 0; t < 2; ++t)
                #pragma unroll
                for (int i = 0; i < 4; ++i)
                    #pragma unroll
                    for (int j = 0; j < 8; ++j)
                        mma16816(acc[i][j], af[i], bfr[t][j][0], bfr[t][j][1]);
        }
    }

    // fused LayerNorm over the 64-col head group (warp tile N == head group).
    if (DO_LN && tmat <= 1) {
        const float qscale = (tmat == 0) ? 0.125f : 1.0f;
        #pragma unroll
        for (int i = 0; i < 4; ++i) {
            #pragma unroll
            for (int hf = 0; hf < 2; ++hf) {
                float s = 0.f, s2 = 0.f;
                #pragma unroll
                for (int j = 0; j < 8; ++j) {
                    const float c0 = acc[i][j][hf * 2], c1 = acc[i][j][hf * 2 + 1];
                    s += c0 + c1;
                    s2 += c0 * c0 + c1 * c1;
                }
                s  += __shfl_xor_sync(0xffffffffu, s, 1);
                s  += __shfl_xor_sync(0xffffffffu, s, 2);
                s2 += __shfl_xor_sync(0xffffffffu, s2, 1);
                s2 += __shfl_xor_sync(0xffffffffu, s2, 2);
                const float mean = s * (1.f / 64.f);
                const float var  = s2 * (1.f / 64.f) - mean * mean;
                const float rr   = rsqrtf(var + LN_EPS) * qscale;
                #pragma unroll
                for (int j = 0; j < 8; ++j) {
                    acc[i][j][hf * 2]     = (acc[i][j][hf * 2]     - mean) * rr;
                    acc[i][j][hf * 2 + 1] = (acc[i][j][hf * 2 + 1] - mean) * rr;
                }
            }
        }
    }

    // epilogue
    const int mBase = bm + warp_m * 64 + (lane >> 2);
    const int nBase = bnn + warp_n * 64 + (lane & 3) * 2;
    #pragma unroll
    for (int i = 0; i < 4; ++i) {
        #pragma unroll
        for (int j = 0; j < 8; ++j) {
            const int row = mBase + i * 16;
            const int col = nBase + j * 8;
            float2 v0 = make_float2(acc[i][j][0], acc[i][j][1]);
            float2 v1 = make_float2(acc[i][j][2], acc[i][j][3]);
            if (bias) {
                const float b0 = bias[col], b1 = bias[col + 1];
                v0.x += b0; v0.y += b1; v1.x += b0; v1.y += b1;
            }
            if (OUT_HALF) {
                __half* Ch = (__half*)C;
                *(__half2*)(Ch + (size_t)row * DMODEL + col) =
                    __floats2half2_rn(v0.x, v0.y);
                *(__half2*)(Ch + (size_t)(row + 8) * DMODEL + col) =
                    __floats2half2_rn(v1.x, v1.y);
            } else {
                float* Cf = (float*)C;
                *(float2*)(Cf + (size_t)row * DMODEL + col)       = v0;
                *(float2*)(Cf + (size_t)(row + 8) * DMODEL + col) = v1;
            }
        }
    }
}

// ---------------- fp32 -> fp16 (single) ------------------------------------------
__global__ void cvt_h(const float* __restrict__ s, __half* __restrict__ d)
{
    int i = (blockIdx.x * blockDim.x + threadIdx.x) * 4;
    float4 v = *(const float4*)(s + i);
    __half2* p = (__half2*)(d + i);
    p[0] = __floats2half2_rn(v.x, v.y);
    p[1] = __floats2half2_rn(v.z, v.w);
}

// ---------------- weights fp32 -> fp16 hi/lo -------------------------------------
__global__ void cvt_w(const float* __restrict__ w0, const float* __restrict__ w1,
                      const float* __restrict__ w2, const float* __restrict__ w3,
                      __half* __restrict__ hi, __half* __restrict__ lo)
{
    const int seg = blockIdx.x >> 8;
    const float* w = (seg == 0) ? w0 : (seg == 1) ? w1 : (seg == 2) ? w2 : w3;
    int i = ((blockIdx.x & 255) * blockDim.x + threadIdx.x) * 4;
    float4 v = *(const float4*)(w + i);
    __half h0 = __float2half(v.x), h1 = __float2half(v.y);
    __half h2 = __float2half(v.z), h3 = __float2half(v.w);
    __half l0 = __float2half(v.x - __half2float(h0));
    __half l1 = __float2half(v.y - __half2float(h1));
    __half l2 = __float2half(v.z - __half2float(h2));
    __half l3 = __float2half(v.w - __half2float(h3));
    __half2* hp = (__half2*)(hi + seg * NW + i);
    __half2* lp = (__half2*)(lo + seg * NW + i);
    hp[0] = __halves2half2(h0, h1); hp[1] = __halves2half2(h2, h3);
    lp[0] = __halves2half2(l0, l1); lp[1] = __halves2half2(l2, l3);
}

// ---------------- smem-staged gather-attention, shuffle-free scores -------------
// K staged with 16B-chunk XOR swizzle (chunk ^= key&7) so the score phase
// (lane = key, serial 64-dim dot product via LDS.128) is bank-conflict-free.
// V staged in natural layout for the lane = dim output phase.
#define ATT_SMEM (65536 + 1024)   // K 32KB | V 32KB | q 8x128B

__global__ __launch_bounds__(256)
void attn_kernel(const __half* __restrict__ Q, const __half* __restrict__ Kt,
                 const __half* __restrict__ V, const int* __restrict__ idx,
                 __half* __restrict__ oh)
{
    extern __shared__ char sm[];
    const uint32_t sbase = smem_u32(sm);
    const int bn = blockIdx.x;
    const int b  = bn >> 13;
    const int n  = bn & (SEQN - 1);
    const int tid = threadIdx.x;
    const int rowbase = b * SEQN;
    const int ibase = n * KNN;

    // stage K (swizzled) then V: 32 rows x 1024 B each
    const int lrow = tid >> 6;       // 0..3
    const int lchk = tid & 63;       // 16B chunk in row
    #pragma unroll
    for (int p = 0; p < 8; ++p) {
        const int r = p * 4 + lrow;
        const int row = idx[ibase + r];
        const int schk = lchk ^ (r & 7);       // XOR swizzle within 128B groups
        cp16(sbase + (uint32_t)(r * 1024 + schk * 16),
             Kt + ((size_t)(rowbase + row) << 9) + lchk * 8);
    }
    CP_COMMIT();
    #pragma unroll
    for (int p = 0; p < 8; ++p) {
        const int r = p * 4 + lrow;
        const int row = idx[ibase + r];
        cp16(sbase + (uint32_t)(32768 + r * 1024 + lchk * 16),
             V + ((size_t)(rowbase + row) << 9) + lchk * 8);
    }
    CP_COMMIT();

    const int h    = tid >> 5;
    const int lane = tid & 31;
    const int qbase = bn * DMODEL + h * DK;
    // Q already LayerNorm'd and pre-scaled by 1/8 in the GEMM epilogue.
    // lane holds dims {2*lane, 2*lane+1}; park q in smem for broadcast reads.
    const uint32_t qv = *(const uint32_t*)(Q + qbase + lane * 2);
    *(uint32_t*)(sm + 65536 + h * 128 + lane * 4) = qv;
    __syncwarp();

    CP_WAIT1();
    __syncthreads();

    // score phase: lane = key; 8 x (LDS.128 K swizzled + LDS.128 q broadcast)
    float s = 0.f;
    const char* kbase = sm + lane * 1024;
    const char* qb = sm + 65536 + h * 128;
    const int hx = h * 8;
    const int lx = lane & 7;
    #pragma unroll
    for (int i = 0; i < 8; ++i) {
        const uint4 kc = *(const uint4*)(kbase + ((hx + i) ^ lx) * 16);
        const uint4 qc = *(const uint4*)(qb + i * 16);
        float2 k0 = __half22float2(*(const __half2*)&kc.x);
        float2 k1 = __half22float2(*(const __half2*)&kc.y);
        float2 k2 = __half22float2(*(const __half2*)&kc.z);
        float2 k3 = __half22float2(*(const __half2*)&kc.w);
        float2 q0 = __half22float2(*(const __half2*)&qc.x);
        float2 q1 = __half22float2(*(const __half2*)&qc.y);
        float2 q2 = __half22float2(*(const __half2*)&qc.z);
        float2 q3 = __half22float2(*(const __half2*)&qc.w);
        s = fmaf(q0.x, k0.x, s); s = fmaf(q0.y, k0.y, s);
        s = fmaf(q1.x, k1.x, s); s = fmaf(q1.y, k1.y, s);
        s = fmaf(q2.x, k2.x, s); s = fmaf(q2.y, k2.y, s);
        s = fmaf(q3.x, k3.x, s); s = fmaf(q3.y, k3.y, s);
    }

    // softmax across the 32 lanes (= 32 keys)
    const float m = warp_max(s);
    const float e = __expf(s - m);
    const float denom = warp_sum(e);
    const float a = e / denom;

    CP_WAIT0();
    __syncthreads();

    // output phase: lane = dim pair
    float o0 = 0.f, o1 = 0.f;
    #pragma unroll
    for (int k = 0; k < KNN; ++k) {
        const float ak = __shfl_sync(0xffffffffu, a, k);
        const float2 vv = __half22float2(
            *(const __half2*)(sm + 32768 + k * 1024 + h * 128 + lane * 4));
        o0 = fmaf(ak, vv.x, o0);
        o1 = fmaf(ak, vv.y, o1);
    }
    ((__half2*)(oh + qbase))[lane] = __floats2half2_rn(o0, o1);
}

// ---------------- launch ---------------------------------------------------------
extern "C" void kernel_launch(void* const* d_in, const int* in_sizes, int n_in,
                              void* d_out, int out_size)
{
    const float* x    = (const float*)d_in[0];
    const int*   idx  = (const int*)  d_in[1];
    const float* Wq   = (const float*)d_in[2];
    const float* Wk   = (const float*)d_in[3];
    const float* Wv   = (const float*)d_in[4];
    const float* Wout = (const float*)d_in[5];
    const float* bout = (const float*)d_in[6];
    float* out = (float*)d_out;

    static __half *gQ = nullptr, *gK, *gV, *xh, *ah, *wh, *wl;
    if (!gQ) {
        cudaGetSymbolAddress((void**)&gQ, g_Q);
        cudaGetSymbolAddress((void**)&gK, g_K);
        cudaGetSymbolAddress((void**)&gV, g_V);
        cudaGetSymbolAddress((void**)&xh, g_xh);
        cudaGetSymbolAddress((void**)&ah, g_ah);
        cudaGetSymbolAddress((void**)&wh, g_wh);
        cudaGetSymbolAddress((void**)&wl, g_wl);
        cudaFuncSetAttribute((const void*)gemm_f16x2<1, 1>,
                             cudaFuncAttributeMaxDynamicSharedMemorySize, GEMM_SMEM);
        cudaFuncSetAttribute((const void*)gemm_f16x2<0, 0>,
                             cudaFuncAttributeMaxDynamicSharedMemorySize, GEMM_SMEM);
        cudaFuncSetAttribute((const void*)attn_kernel,
                             cudaFuncAttributeMaxDynamicSharedMemorySize, ATT_SMEM);
    }

    // conversions
    cvt_h<<<NX / 1024, 256>>>(x, xh);
    cvt_w<<<1024, 256>>>(Wq, Wk, Wv, Wout, wh, wl);

    // fused Q,K,V projections -> fp16 outputs; LN fused for Q (x1/8) and K
    gemm_f16x2<1, 1><<<dim3(12, 64), 256, GEMM_SMEM>>>(xh, wh, wl, gQ, gK, gV,
                                                       nullptr);

    // smem-staged attention, shuffle-free score phase
    attn_kernel<<<MROWS, 256, ATT_SMEM>>>(gQ, gK, gV, idx, ah);

    // output projection + bias -> fp32 d_out
    gemm_f16x2<0, 0><<<dim3(4, 64), 256, GEMM_SMEM>>>(ah, wh + 3 * (size_t)NW,
                                                      wl + 3 * (size_t)NW,
                                                      out, out, out, bout);
}

// round 11
// speedup vs baseline: 3.5614x; 1.1970x over previous
#include <cuda_runtime.h>
#include <cuda_fp16.h>
#include <cstdint>

// Problem constants
#define BATCH 2
#define SEQN  8192
#define DMODEL 512
#define HEADS 8
#define DK 64
#define KNN 32
#define MROWS (BATCH*SEQN)   // 16384
#define LN_EPS 1e-5f
#define NW (DMODEL*DMODEL)   // 262144
#define NX (MROWS*DMODEL)    // 8388608

// ---------------- scratch (device globals; no allocation allowed) -------------
__device__ __align__(128) __half g_Q[NX];
__device__ __align__(128) __half g_K[NX];
__device__ __align__(128) __half g_V[NX];
__device__ __align__(128) __half g_xh[NX];        // x in fp16
__device__ __align__(128) __half g_ah[NX];        // attention out in fp16
__device__ __align__(128) __half g_wh[4 * NW];    // weights fp16 hi
__device__ __align__(128) __half g_wl[4 * NW];    // weights fp16 lo (used by out-proj)

// ---------------- small helpers -------------------------------------------------
__device__ __forceinline__ uint32_t smem_u32(const void* p) {
    uint32_t a;
    asm("{ .reg .u64 t; cvta.to.shared.u64 t, %1; cvt.u32.u64 %0, t; }"
        : "=r"(a) : "l"(p));
    return a;
}
__device__ __forceinline__ void ldsm_x4(uint32_t (&r)[4], uint32_t addr) {
    asm volatile("ldmatrix.sync.aligned.m8n8.x4.shared.b16 {%0,%1,%2,%3}, [%4];"
                 : "=r"(r[0]), "=r"(r[1]), "=r"(r[2]), "=r"(r[3]) : "r"(addr));
}
__device__ __forceinline__ void mma16816(float (&c)[4], const uint32_t (&a)[4],
                                         const uint32_t b0, const uint32_t b1) {
    asm volatile("mma.sync.aligned.m16n8k16.row.col.f32.f16.f16.f32 "
                 "{%0,%1,%2,%3}, {%4,%5,%6,%7}, {%8,%9}, {%0,%1,%2,%3};"
                 : "+f"(c[0]), "+f"(c[1]), "+f"(c[2]), "+f"(c[3])
                 : "r"(a[0]), "r"(a[1]), "r"(a[2]), "r"(a[3]), "r"(b0), "r"(b1));
}
__device__ __forceinline__ void cp16(uint32_t saddr, const void* gaddr) {
    asm volatile("cp.async.cg.shared.global [%0], [%1], 16;"
                 :: "r"(saddr), "l"(gaddr) : "memory");
}
#define CP_COMMIT() asm volatile("cp.async.commit_group;" ::: "memory")
#define CP_WAIT1()  asm volatile("cp.async.wait_group 1;" ::: "memory")
#define CP_WAIT0()  asm volatile("cp.async.wait_group 0;" ::: "memory")

__device__ __forceinline__ float warp_sum(float v) {
    v += __shfl_xor_sync(0xffffffffu, v, 16);
    v += __shfl_xor_sync(0xffffffffu, v, 8);
    v += __shfl_xor_sync(0xffffffffu, v, 4);
    v += __shfl_xor_sync(0xffffffffu, v, 2);
    v += __shfl_xor_sync(0xffffffffu, v, 1);
    return v;
}
__device__ __forceinline__ float warp_max(float v) {
    v = fmaxf(v, __shfl_xor_sync(0xffffffffu, v, 16));
    v = fmaxf(v, __shfl_xor_sync(0xffffffffu, v, 8));
    v = fmaxf(v, __shfl_xor_sync(0xffffffffu, v, 4));
    v = fmaxf(v, __shfl_xor_sync(0xffffffffu, v, 2));
    v = fmaxf(v, __shfl_xor_sync(0xffffffffu, v, 1));
    return v;
}

// ---------------- GEMM: C_t = A(16384x512,fp16) * W_t^T -------------------------
// TWO_TERM=1: W as exact fp16 hi/lo pair (2 MMAs per k-step).
// TWO_TERM=0: single fp16 W (1 MMA per k-step).
// CTA tile 256(M) x 128(N), BK=32, 8 warps (4m x 2n), warp tile 64x64.
// 3-stage cp.async. OUT_HALF: fp16 vs fp32 output. DO_LN: fused per-64-col
// LayerNorm on tmat 0 (with 1/8 scale) and tmat 1 in the epilogue.
#define BKC 32
#define NCH (DMODEL / BKC)     // 16
#define PITCH 40               // fp16 elems per smem row (80B, conflict-free ldmatrix)
#define TILE_A_B (256 * PITCH * 2)      // 20480 B
#define TILE_B_B (128 * PITCH * 2)      // 10240 B
#define NSTAGE 3
#define GEMM_SMEM_1 (NSTAGE * (TILE_A_B + TILE_B_B))       // 92160 B
#define GEMM_SMEM_2 (NSTAGE * (TILE_A_B + 2 * TILE_B_B))   // 122880 B

template <int OUT_HALF, int DO_LN, int TWO_TERM>
__global__ __launch_bounds__(256, 1)
void gemm_f16(const __half* __restrict__ A,
              const __half* __restrict__ Wh, const __half* __restrict__ Wl,
              void* __restrict__ C0, void* __restrict__ C1, void* __restrict__ C2,
              const float* __restrict__ bias)
{
    extern __shared__ char smem[];
    const uint32_t sbase = smem_u32(smem);
    const int tid  = threadIdx.x;
    const int wid  = tid >> 5;
    const int lane = tid & 31;

    constexpr int STAGE_B = TILE_A_B + (TWO_TERM ? 2 : 1) * TILE_B_B;

    const int tmat = blockIdx.x >> 2;
    const int bnn  = (blockIdx.x & 3) * 128;
    const int bm   = blockIdx.y * 256;
    const int warp_m = wid & 3;
    const int warp_n = wid >> 2;

    const __half* Bh = Wh + (size_t)tmat * NW;
    const __half* Bl = Wl + (size_t)tmat * NW;
    void* C = (tmat == 0) ? C0 : (tmat == 1) ? C1 : C2;

    const int lr = tid >> 2;
    const int lc = tid & 3;

    auto load_stage = [&](int c, int buf) {
        const uint32_t s0 = sbase + buf * STAGE_B;
        const int kc = c * BKC;
        #pragma unroll
        for (int p = 0; p < 4; ++p) {
            const int r = lr + p * 64;
            cp16(s0 + (uint32_t)(r * (PITCH * 2) + lc * 16),
                 A + (size_t)(bm + r) * DMODEL + kc + lc * 8);
        }
        #pragma unroll
        for (int t = 0; t < (TWO_TERM ? 2 : 1); ++t) {
            const __half* g = t ? Bl : Bh;
            const uint32_t tb = s0 + TILE_A_B + t * TILE_B_B;
            #pragma unroll
            for (int p = 0; p < 2; ++p) {
                const int r = lr + p * 64;
                cp16(tb + (uint32_t)(r * (PITCH * 2) + lc * 16),
                     g + (size_t)(bnn + r) * DMODEL + kc + lc * 8);
            }
        }
        CP_COMMIT();
    };

    float acc[4][8][4];
    #pragma unroll
    for (int i = 0; i < 4; i++)
        #pragma unroll
        for (int j = 0; j < 8; j++)
            #pragma unroll
            for (int r = 0; r < 4; r++) acc[i][j][r] = 0.f;

    load_stage(0, 0);
    load_stage(1, 1);

    const int aRow  = lane & 15;
    const int aColB = (lane >> 4) * 8;
    const int quad  = lane >> 3;
    const int bRowL = (quad >> 1) * 8 + (lane & 7);
    const int bColB = (quad & 1) * 8;

    #pragma unroll 1
    for (int c = 0; c < NCH; ++c) {
        const int buf = c % NSTAGE;
        if (c + 1 < NCH) CP_WAIT1(); else CP_WAIT0();
        __syncthreads();
        if (c + 2 < NCH) load_stage(c + 2, (c + 2) % NSTAGE);

        const uint32_t sA  = sbase + buf * STAGE_B;
        const uint32_t sBh = sA + TILE_A_B;
        const uint32_t sBl = sBh + TILE_B_B;

        #pragma unroll
        for (int ks = 0; ks < 2; ++ks) {
            uint32_t af[4][4];
            uint32_t bfr[2][8][2];
            #pragma unroll
            for (int i = 0; i < 4; ++i) {
                const uint32_t ao = (uint32_t)((warp_m * 64 + i * 16 + aRow) * PITCH
                                               + ks * 16 + aColB) * 2;
                ldsm_x4(af[i], sA + ao);
            }
            #pragma unroll
            for (int p = 0; p < 4; ++p) {
                const uint32_t bo = (uint32_t)((warp_n * 64 + p * 16 + bRowL) * PITCH
                                               + ks * 16 + bColB) * 2;
                uint32_t r0[4];
                ldsm_x4(r0, sBh + bo);
                bfr[0][2*p][0]   = r0[0]; bfr[0][2*p][1]   = r0[1];
                bfr[0][2*p+1][0] = r0[2]; bfr[0][2*p+1][1] = r0[3];
                if (TWO_TERM) {
                    uint32_t r1[4];
                    ldsm_x4(r1, sBl + bo);
                    bfr[1][2*p][0]   = r1[0]; bfr[1][2*p][1]   = r1[1];
                    bfr[1][2*p+1][0] = r1[2]; bfr[1][2*p+1][1] = r1[3];
                }
            }
            #pragma unroll
            for (int t = 0; t < (TWO_TERM ? 2 : 1); ++t)
                #pragma unroll
                for (int i = 0; i < 4; ++i)
                    #pragma unroll
                    for (int j = 0; j < 8; ++j)
                        mma16816(acc[i][j], af[i], bfr[t][j][0], bfr[t][j][1]);
        }
    }

    // fused LayerNorm over the 64-col head group (warp tile N == head group).
    if (DO_LN && tmat <= 1) {
        const float qscale = (tmat == 0) ? 0.125f : 1.0f;
        #pragma unroll
        for (int i = 0; i < 4; ++i) {
            #pragma unroll
            for (int hf = 0; hf < 2; ++hf) {
                float s = 0.f, s2 = 0.f;
                #pragma unroll
                for (int j = 0; j < 8; ++j) {
                    const float c0 = acc[i][j][hf * 2], c1 = acc[i][j][hf * 2 + 1];
                    s += c0 + c1;
                    s2 += c0 * c0 + c1 * c1;
                }
                s  += __shfl_xor_sync(0xffffffffu, s, 1);
                s  += __shfl_xor_sync(0xffffffffu, s, 2);
                s2 += __shfl_xor_sync(0xffffffffu, s2, 1);
                s2 += __shfl_xor_sync(0xffffffffu, s2, 2);
                const float mean = s * (1.f / 64.f);
                const float var  = s2 * (1.f / 64.f) - mean * mean;
                const float rr   = rsqrtf(var + LN_EPS) * qscale;
                #pragma unroll
                for (int j = 0; j < 8; ++j) {
                    acc[i][j][hf * 2]     = (acc[i][j][hf * 2]     - mean) * rr;
                    acc[i][j][hf * 2 + 1] = (acc[i][j][hf * 2 + 1] - mean) * rr;
                }
            }
        }
    }

    // epilogue
    const int mBase = bm + warp_m * 64 + (lane >> 2);
    const int nBase = bnn + warp_n * 64 + (lane & 3) * 2;
    #pragma unroll
    for (int i = 0; i < 4; ++i) {
        #pragma unroll
        for (int j = 0; j < 8; ++j) {
            const int row = mBase + i * 16;
            const int col = nBase + j * 8;
            float2 v0 = make_float2(acc[i][j][0], acc[i][j][1]);
            float2 v1 = make_float2(acc[i][j][2], acc[i][j][3]);
            if (bias) {
                const float b0 = bias[col], b1 = bias[col + 1];
                v0.x += b0; v0.y += b1; v1.x += b0; v1.y += b1;
            }
            if (OUT_HALF) {
                __half* Ch = (__half*)C;
                *(__half2*)(Ch + (size_t)row * DMODEL + col) =
                    __floats2half2_rn(v0.x, v0.y);
                *(__half2*)(Ch + (size_t)(row + 8) * DMODEL + col) =
                    __floats2half2_rn(v1.x, v1.y);
            } else {
                float* Cf = (float*)C;
                *(float2*)(Cf + (size_t)row * DMODEL + col)       = v0;
                *(float2*)(Cf + (size_t)(row + 8) * DMODEL + col) = v1;
            }
        }
    }
}

// ---------------- fp32 -> fp16 (single) ------------------------------------------
__global__ void cvt_h(const float* __restrict__ s, __half* __restrict__ d)
{
    int i = (blockIdx.x * blockDim.x + threadIdx.x) * 4;
    float4 v = *(const float4*)(s + i);
    __half2* p = (__half2*)(d + i);
    p[0] = __floats2half2_rn(v.x, v.y);
    p[1] = __floats2half2_rn(v.z, v.w);
}

// ---------------- weights fp32 -> fp16 hi/lo -------------------------------------
__global__ void cvt_w(const float* __restrict__ w0, const float* __restrict__ w1,
                      const float* __restrict__ w2, const float* __restrict__ w3,
                      __half* __restrict__ hi, __half* __restrict__ lo)
{
    const int seg = blockIdx.x >> 8;
    const float* w = (seg == 0) ? w0 : (seg == 1) ? w1 : (seg == 2) ? w2 : w3;
    int i = ((blockIdx.x & 255) * blockDim.x + threadIdx.x) * 4;
    float4 v = *(const float4*)(w + i);
    __half h0 = __float2half(v.x), h1 = __float2half(v.y);
    __half h2 = __float2half(v.z), h3 = __float2half(v.w);
    __half l0 = __float2half(v.x - __half2float(h0));
    __half l1 = __float2half(v.y - __half2float(h1));
    __half l2 = __float2half(v.z - __half2float(h2));
    __half l3 = __float2half(v.w - __half2float(h3));
    __half2* hp = (__half2*)(hi + seg * NW + i);
    __half2* lp = (__half2*)(lo + seg * NW + i);
    hp[0] = __halves2half2(h0, h1); hp[1] = __halves2half2(h2, h3);
    lp[0] = __halves2half2(l0, l1); lp[1] = __halves2half2(l2, l3);
}

// ---------------- smem-staged gather-attention, shuffle-free scores -------------
#define ATT_SMEM (65536 + 1024)   // K 32KB | V 32KB | q 8x128B

__global__ __launch_bounds__(256)
void attn_kernel(const __half* __restrict__ Q, const __half* __restrict__ Kt,
                 const __half* __restrict__ V, const int* __restrict__ idx,
                 __half* __restrict__ oh)
{
    extern __shared__ char sm[];
    const uint32_t sbase = smem_u32(sm);
    const int bn = blockIdx.x;
    const int b  = bn >> 13;
    const int n  = bn & (SEQN - 1);
    const int tid = threadIdx.x;
    const int rowbase = b * SEQN;
    const int ibase = n * KNN;

    // stage K (swizzled) then V: 32 rows x 1024 B each
    const int lrow = tid >> 6;       // 0..3
    const int lchk = tid & 63;       // 16B chunk in row
    #pragma unroll
    for (int p = 0; p < 8; ++p) {
        const int r = p * 4 + lrow;
        const int row = idx[ibase + r];
        const int schk = lchk ^ (r & 7);       // XOR swizzle within 128B groups
        cp16(sbase + (uint32_t)(r * 1024 + schk * 16),
             Kt + ((size_t)(rowbase + row) << 9) + lchk * 8);
    }
    CP_COMMIT();
    #pragma unroll
    for (int p = 0; p < 8; ++p) {
        const int r = p * 4 + lrow;
        const int row = idx[ibase + r];
        cp16(sbase + (uint32_t)(32768 + r * 1024 + lchk * 16),
             V + ((size_t)(rowbase + row) << 9) + lchk * 8);
    }
    CP_COMMIT();

    const int h    = tid >> 5;
    const int lane = tid & 31;
    const int qbase = bn * DMODEL + h * DK;
    // Q already LayerNorm'd and pre-scaled by 1/8 in the GEMM epilogue.
    const uint32_t qv = *(const uint32_t*)(Q + qbase + lane * 2);
    *(uint32_t*)(sm + 65536 + h * 128 + lane * 4) = qv;
    __syncwarp();

    CP_WAIT1();
    __syncthreads();

    // score phase: lane = key; 8 x (LDS.128 K swizzled + LDS.128 q broadcast)
    float s = 0.f;
    const char* kbase = sm + lane * 1024;
    const char* qb = sm + 65536 + h * 128;
    const int hx = h * 8;
    const int lx = lane & 7;
    #pragma unroll
    for (int i = 0; i < 8; ++i) {
        const uint4 kc = *(const uint4*)(kbase + ((hx + i) ^ lx) * 16);
        const uint4 qc = *(const uint4*)(qb + i * 16);
        float2 k0 = __half22float2(*(const __half2*)&kc.x);
        float2 k1 = __half22float2(*(const __half2*)&kc.y);
        float2 k2 = __half22float2(*(const __half2*)&kc.z);
        float2 k3 = __half22float2(*(const __half2*)&kc.w);
        float2 q0 = __half22float2(*(const __half2*)&qc.x);
        float2 q1 = __half22float2(*(const __half2*)&qc.y);
        float2 q2 = __half22float2(*(const __half2*)&qc.z);
        float2 q3 = __half22float2(*(const __half2*)&qc.w);
        s = fmaf(q0.x, k0.x, s); s = fmaf(q0.y, k0.y, s);
        s = fmaf(q1.x, k1.x, s); s = fmaf(q1.y, k1.y, s);
        s = fmaf(q2.x, k2.x, s); s = fmaf(q2.y, k2.y, s);
        s = fmaf(q3.x, k3.x, s); s = fmaf(q3.y, k3.y, s);
    }

    // softmax across the 32 lanes (= 32 keys)
    const float m = warp_max(s);
    const float e = __expf(s - m);
    const float denom = warp_sum(e);
    const float a = e / denom;

    CP_WAIT0();
    __syncthreads();

    // output phase: lane = dim pair
    float o0 = 0.f, o1 = 0.f;
    #pragma unroll
    for (int k = 0; k < KNN; ++k) {
        const float ak = __shfl_sync(0xffffffffu, a, k);
        const float2 vv = __half22float2(
            *(const __half2*)(sm + 32768 + k * 1024 + h * 128 + lane * 4));
        o0 = fmaf(ak, vv.x, o0);
        o1 = fmaf(ak, vv.y, o1);
    }
    ((__half2*)(oh + qbase))[lane] = __floats2half2_rn(o0, o1);
}

// ---------------- launch ---------------------------------------------------------
extern "C" void kernel_launch(void* const* d_in, const int* in_sizes, int n_in,
                              void* d_out, int out_size)
{
    const float* x    = (const float*)d_in[0];
    const int*   idx  = (const int*)  d_in[1];
    const float* Wq   = (const float*)d_in[2];
    const float* Wk   = (const float*)d_in[3];
    const float* Wv   = (const float*)d_in[4];
    const float* Wout = (const float*)d_in[5];
    const float* bout = (const float*)d_in[6];
    float* out = (float*)d_out;

    static __half *gQ = nullptr, *gK, *gV, *xh, *ah, *wh, *wl;
    if (!gQ) {
        cudaGetSymbolAddress((void**)&gQ, g_Q);
        cudaGetSymbolAddress((void**)&gK, g_K);
        cudaGetSymbolAddress((void**)&gV, g_V);
        cudaGetSymbolAddress((void**)&xh, g_xh);
        cudaGetSymbolAddress((void**)&ah, g_ah);
        cudaGetSymbolAddress((void**)&wh, g_wh);
        cudaGetSymbolAddress((void**)&wl, g_wl);
        cudaFuncSetAttribute((const void*)gemm_f16<1, 1, 0>,
                             cudaFuncAttributeMaxDynamicSharedMemorySize, GEMM_SMEM_1);
        cudaFuncSetAttribute((const void*)gemm_f16<0, 0, 1>,
                             cudaFuncAttributeMaxDynamicSharedMemorySize, GEMM_SMEM_2);
        cudaFuncSetAttribute((const void*)attn_kernel,
                             cudaFuncAttributeMaxDynamicSharedMemorySize, ATT_SMEM);
    }

    // conversions
    cvt_h<<<NX / 1024, 256>>>(x, xh);
    cvt_w<<<1024, 256>>>(Wq, Wk, Wv, Wout, wh, wl);

    // fused Q,K,V projections (single fp16 weight term) -> fp16; LN fused
    gemm_f16<1, 1, 0><<<dim3(12, 64), 256, GEMM_SMEM_1>>>(xh, wh, wl, gQ, gK, gV,
                                                          nullptr);

    // smem-staged attention, shuffle-free score phase
    attn_kernel<<<MROWS, 256, ATT_SMEM>>>(gQ, gK, gV, idx, ah);

    // output projection (exact 2-term) + bias -> fp32 d_out
    gemm_f16<0, 0, 1><<<dim3(4, 64), 256, GEMM_SMEM_2>>>(ah, wh + 3 * (size_t)NW,
                                                         wl + 3 * (size_t)NW,
                                                         out, out, out, bout);
}

// round 12
// speedup vs baseline: 4.0326x; 1.1323x over previous
#include <cuda_runtime.h>
#include <cuda_fp16.h>
#include <cstdint>

// Problem constants
#define BATCH 2
#define SEQN  8192
#define DMODEL 512
#define HEADS 8
#define DK 64
#define KNN 32
#define MROWS (BATCH*SEQN)   // 16384
#define LN_EPS 1e-5f
#define NW (DMODEL*DMODEL)   // 262144
#define NX (MROWS*DMODEL)    // 8388608

// ---------------- scratch (device globals; no allocation allowed) -------------
__device__ __align__(128) __half g_Q[NX];
__device__ __align__(128) __half g_K[NX];
__device__ __align__(128) __half g_V[NX];
__device__ __align__(128) __half g_xh[NX];        // x in fp16
__device__ __align__(128) __half g_ah[NX];        // attention out in fp16
__device__ __align__(128) __half g_wh[4 * NW];    // weights fp16

// ---------------- small helpers -------------------------------------------------
__device__ __forceinline__ uint32_t smem_u32(const void* p) {
    uint32_t a;
    asm("{ .reg .u64 t; cvta.to.shared.u64 t, %1; cvt.u32.u64 %0, t; }"
        : "=r"(a) : "l"(p));
    return a;
}
__device__ __forceinline__ void ldsm_x4(uint32_t (&r)[4], uint32_t addr) {
    asm volatile("ldmatrix.sync.aligned.m8n8.x4.shared.b16 {%0,%1,%2,%3}, [%4];"
                 : "=r"(r[0]), "=r"(r[1]), "=r"(r[2]), "=r"(r[3]) : "r"(addr));
}
__device__ __forceinline__ void mma16816(float (&c)[4], const uint32_t (&a)[4],
                                         const uint32_t b0, const uint32_t b1) {
    asm volatile("mma.sync.aligned.m16n8k16.row.col.f32.f16.f16.f32 "
                 "{%0,%1,%2,%3}, {%4,%5,%6,%7}, {%8,%9}, {%0,%1,%2,%3};"
                 : "+f"(c[0]), "+f"(c[1]), "+f"(c[2]), "+f"(c[3])
                 : "r"(a[0]), "r"(a[1]), "r"(a[2]), "r"(a[3]), "r"(b0), "r"(b1));
}
__device__ __forceinline__ void cp16(uint32_t saddr, const void* gaddr) {
    asm volatile("cp.async.cg.shared.global [%0], [%1], 16;"
                 :: "r"(saddr), "l"(gaddr) : "memory");
}
#define CP_COMMIT() asm volatile("cp.async.commit_group;" ::: "memory")
#define CP_WAIT1()  asm volatile("cp.async.wait_group 1;" ::: "memory")
#define CP_WAIT0()  asm volatile("cp.async.wait_group 0;" ::: "memory")

__device__ __forceinline__ float warp_sum(float v) {
    v += __shfl_xor_sync(0xffffffffu, v, 16);
    v += __shfl_xor_sync(0xffffffffu, v, 8);
    v += __shfl_xor_sync(0xffffffffu, v, 4);
    v += __shfl_xor_sync(0xffffffffu, v, 2);
    v += __shfl_xor_sync(0xffffffffu, v, 1);
    return v;
}
__device__ __forceinline__ float warp_max(float v) {
    v = fmaxf(v, __shfl_xor_sync(0xffffffffu, v, 16));
    v = fmaxf(v, __shfl_xor_sync(0xffffffffu, v, 8));
    v = fmaxf(v, __shfl_xor_sync(0xffffffffu, v, 4));
    v = fmaxf(v, __shfl_xor_sync(0xffffffffu, v, 2));
    v = fmaxf(v, __shfl_xor_sync(0xffffffffu, v, 1));
    return v;
}

// ---------------- GEMM: C_t = A(16384x512,fp16) * W_t^T (single fp16 W) ---------
// CTA tile 256(M) x 128(N), BK=32, 8 warps (4m x 2n), warp tile 64x64.
// 3-stage cp.async. OUT_HALF: fp16 vs fp32 output. DO_LN: fused per-64-col
// LayerNorm on tmat 0 (with 1/8 scale) and tmat 1 in the epilogue.
#define BKC 32
#define NCH (DMODEL / BKC)     // 16
#define PITCH 40               // fp16 elems per smem row (80B, conflict-free ldmatrix)
#define TILE_A_B (256 * PITCH * 2)      // 20480 B
#define TILE_B_B (128 * PITCH * 2)      // 10240 B
#define STAGE_B (TILE_A_B + TILE_B_B)   // 30720 B
#define NSTAGE 3
#define GEMM_SMEM (NSTAGE * STAGE_B)    // 92160 B

template <int OUT_HALF, int DO_LN>
__global__ __launch_bounds__(256, 1)
void gemm_f16(const __half* __restrict__ A, const __half* __restrict__ Wh,
              void* __restrict__ C0, void* __restrict__ C1, void* __restrict__ C2,
              const float* __restrict__ bias)
{
    extern __shared__ char smem[];
    const uint32_t sbase = smem_u32(smem);
    const int tid  = threadIdx.x;
    const int wid  = tid >> 5;
    const int lane = tid & 31;

    const int tmat = blockIdx.x >> 2;
    const int bnn  = (blockIdx.x & 3) * 128;
    const int bm   = blockIdx.y * 256;
    const int warp_m = wid & 3;
    const int warp_n = wid >> 2;

    const __half* Bh = Wh + (size_t)tmat * NW;
    void* C = (tmat == 0) ? C0 : (tmat == 1) ? C1 : C2;

    const int lr = tid >> 2;
    const int lc = tid & 3;

    auto load_stage = [&](int c, int buf) {
        const uint32_t s0 = sbase + buf * STAGE_B;
        const int kc = c * BKC;
        #pragma unroll
        for (int p = 0; p < 4; ++p) {
            const int r = lr + p * 64;
            cp16(s0 + (uint32_t)(r * (PITCH * 2) + lc * 16),
                 A + (size_t)(bm + r) * DMODEL + kc + lc * 8);
        }
        #pragma unroll
        for (int p = 0; p < 2; ++p) {
            const int r = lr + p * 64;
            cp16(s0 + TILE_A_B + (uint32_t)(r * (PITCH * 2) + lc * 16),
                 Bh + (size_t)(bnn + r) * DMODEL + kc + lc * 8);
        }
        CP_COMMIT();
    };

    float acc[4][8][4];
    #pragma unroll
    for (int i = 0; i < 4; i++)
        #pragma unroll
        for (int j = 0; j < 8; j++)
            #pragma unroll
            for (int r = 0; r < 4; r++) acc[i][j][r] = 0.f;

    load_stage(0, 0);
    load_stage(1, 1);

    const int aRow  = lane & 15;
    const int aColB = (lane >> 4) * 8;
    const int quad  = lane >> 3;
    const int bRowL = (quad >> 1) * 8 + (lane & 7);
    const int bColB = (quad & 1) * 8;

    #pragma unroll 1
    for (int c = 0; c < NCH; ++c) {
        const int buf = c % NSTAGE;
        if (c + 1 < NCH) CP_WAIT1(); else CP_WAIT0();
        __syncthreads();
        if (c + 2 < NCH) load_stage(c + 2, (c + 2) % NSTAGE);

        const uint32_t sA  = sbase + buf * STAGE_B;
        const uint32_t sBh = sA + TILE_A_B;

        #pragma unroll
        for (int ks = 0; ks < 2; ++ks) {
            uint32_t af[4][4];
            uint32_t bfr[8][2];
            #pragma unroll
            for (int i = 0; i < 4; ++i) {
                const uint32_t ao = (uint32_t)((warp_m * 64 + i * 16 + aRow) * PITCH
                                               + ks * 16 + aColB) * 2;
                ldsm_x4(af[i], sA + ao);
            }
            #pragma unroll
            for (int p = 0; p < 4; ++p) {
                const uint32_t bo = (uint32_t)((warp_n * 64 + p * 16 + bRowL) * PITCH
                                               + ks * 16 + bColB) * 2;
                uint32_t r0[4];
                ldsm_x4(r0, sBh + bo);
                bfr[2*p][0]   = r0[0]; bfr[2*p][1]   = r0[1];
                bfr[2*p+1][0] = r0[2]; bfr[2*p+1][1] = r0[3];
            }
            #pragma unroll
            for (int i = 0; i < 4; ++i)
                #pragma unroll
                for (int j = 0; j < 8; ++j)
                    mma16816(acc[i][j], af[i], bfr[j][0], bfr[j][1]);
        }
    }

    // fused LayerNorm over the 64-col head group (warp tile N == head group).
    if (DO_LN && tmat <= 1) {
        const float qscale = (tmat == 0) ? 0.125f : 1.0f;
        #pragma unroll
        for (int i = 0; i < 4; ++i) {
            #pragma unroll
            for (int hf = 0; hf < 2; ++hf) {
                float s = 0.f, s2 = 0.f;
                #pragma unroll
                for (int j = 0; j < 8; ++j) {
                    const float c0 = acc[i][j][hf * 2], c1 = acc[i][j][hf * 2 + 1];
                    s += c0 + c1;
                    s2 += c0 * c0 + c1 * c1;
                }
                s  += __shfl_xor_sync(0xffffffffu, s, 1);
                s  += __shfl_xor_sync(0xffffffffu, s, 2);
                s2 += __shfl_xor_sync(0xffffffffu, s2, 1);
                s2 += __shfl_xor_sync(0xffffffffu, s2, 2);
                const float mean = s * (1.f / 64.f);
                const float var  = s2 * (1.f / 64.f) - mean * mean;
                const float rr   = rsqrtf(var + LN_EPS) * qscale;
                #pragma unroll
                for (int j = 0; j < 8; ++j) {
                    acc[i][j][hf * 2]     = (acc[i][j][hf * 2]     - mean) * rr;
                    acc[i][j][hf * 2 + 1] = (acc[i][j][hf * 2 + 1] - mean) * rr;
                }
            }
        }
    }

    // epilogue
    const int mBase = bm + warp_m * 64 + (lane >> 2);
    const int nBase = bnn + warp_n * 64 + (lane & 3) * 2;
    #pragma unroll
    for (int i = 0; i < 4; ++i) {
        #pragma unroll
        for (int j = 0; j < 8; ++j) {
            const int row = mBase + i * 16;
            const int col = nBase + j * 8;
            float2 v0 = make_float2(acc[i][j][0], acc[i][j][1]);
            float2 v1 = make_float2(acc[i][j][2], acc[i][j][3]);
            if (bias) {
                const float b0 = bias[col], b1 = bias[col + 1];
                v0.x += b0; v0.y += b1; v1.x += b0; v1.y += b1;
            }
            if (OUT_HALF) {
                __half* Ch = (__half*)C;
                *(__half2*)(Ch + (size_t)row * DMODEL + col) =
                    __floats2half2_rn(v0.x, v0.y);
                *(__half2*)(Ch + (size_t)(row + 8) * DMODEL + col) =
                    __floats2half2_rn(v1.x, v1.y);
            } else {
                float* Cf = (float*)C;
                *(float2*)(Cf + (size_t)row * DMODEL + col)       = v0;
                *(float2*)(Cf + (size_t)(row + 8) * DMODEL + col) = v1;
            }
        }
    }
}

// ---------------- fp32 -> fp16 (single) ------------------------------------------
__global__ void cvt_h(const float* __restrict__ s, __half* __restrict__ d)
{
    int i = (blockIdx.x * blockDim.x + threadIdx.x) * 4;
    float4 v = *(const float4*)(s + i);
    __half2* p = (__half2*)(d + i);
    p[0] = __floats2half2_rn(v.x, v.y);
    p[1] = __floats2half2_rn(v.z, v.w);
}

// ---------------- weights fp32 -> fp16 --------------------------------------------
__global__ void cvt_w(const float* __restrict__ w0, const float* __restrict__ w1,
                      const float* __restrict__ w2, const float* __restrict__ w3,
                      __half* __restrict__ hi)
{
    const int seg = blockIdx.x >> 8;
    const float* w = (seg == 0) ? w0 : (seg == 1) ? w1 : (seg == 2) ? w2 : w3;
    int i = ((blockIdx.x & 255) * blockDim.x + threadIdx.x) * 4;
    float4 v = *(const float4*)(w + i);
    __half2* hp = (__half2*)(hi + seg * NW + i);
    hp[0] = __floats2half2_rn(v.x, v.y);
    hp[1] = __floats2half2_rn(v.z, v.w);
}

// ---------------- gather-attention: K staged (swizzled), V from global ----------
// smem: K 32KB | q 1KB | rows 128B  -> 6 blocks/SM (vs 3 with V staged)
#define ATT_SMEM (32768 + 1024 + 128)

__global__ __launch_bounds__(256)
void attn_kernel(const __half* __restrict__ Q, const __half* __restrict__ Kt,
                 const __half* __restrict__ V, const int* __restrict__ idx,
                 __half* __restrict__ oh)
{
    extern __shared__ char sm[];
    const uint32_t sbase = smem_u32(sm);
    int* srows = (int*)(sm + 32768 + 1024);
    const int bn = blockIdx.x;
    const int b  = bn >> 13;
    const int n  = bn & (SEQN - 1);
    const int tid = threadIdx.x;
    const int rowbase = b * SEQN;
    const int ibase = n * KNN;

    if (tid < KNN) srows[tid] = idx[ibase + tid];

    // stage K (swizzled): 32 rows x 1024 B
    const int lrow = tid >> 6;       // 0..3
    const int lchk = tid & 63;       // 16B chunk in row
    #pragma unroll
    for (int p = 0; p < 8; ++p) {
        const int r = p * 4 + lrow;
        const int row = idx[ibase + r];
        const int schk = lchk ^ (r & 7);       // XOR swizzle within 128B groups
        cp16(sbase + (uint32_t)(r * 1024 + schk * 16),
             Kt + ((size_t)(rowbase + row) << 9) + lchk * 8);
    }
    CP_COMMIT();

    const int h    = tid >> 5;
    const int lane = tid & 31;
    const int qbase = bn * DMODEL + h * DK;
    // Q already LayerNorm'd and pre-scaled by 1/8 in the GEMM epilogue.
    const uint32_t qv = *(const uint32_t*)(Q + qbase + lane * 2);
    *(uint32_t*)(sm + 32768 + h * 128 + lane * 4) = qv;

    CP_WAIT0();
    __syncthreads();

    // score phase: lane = key; 8 x (LDS.128 K swizzled + LDS.128 q broadcast)
    float s = 0.f;
    const char* kbase = sm + lane * 1024;
    const char* qb = sm + 32768 + h * 128;
    const int hx = h * 8;
    const int lx = lane & 7;
    #pragma unroll
    for (int i = 0; i < 8; ++i) {
        const uint4 kc = *(const uint4*)(kbase + ((hx + i) ^ lx) * 16);
        const uint4 qc = *(const uint4*)(qb + i * 16);
        float2 k0 = __half22float2(*(const __half2*)&kc.x);
        float2 k1 = __half22float2(*(const __half2*)&kc.y);
        float2 k2 = __half22float2(*(const __half2*)&kc.z);
        float2 k3 = __half22float2(*(const __half2*)&kc.w);
        float2 q0 = __half22float2(*(const __half2*)&qc.x);
        float2 q1 = __half22float2(*(const __half2*)&qc.y);
        float2 q2 = __half22float2(*(const __half2*)&qc.z);
        float2 q3 = __half22float2(*(const __half2*)&qc.w);
        s = fmaf(q0.x, k0.x, s); s = fmaf(q0.y, k0.y, s);
        s = fmaf(q1.x, k1.x, s); s = fmaf(q1.y, k1.y, s);
        s = fmaf(q2.x, k2.x, s); s = fmaf(q2.y, k2.y, s);
        s = fmaf(q3.x, k3.x, s); s = fmaf(q3.y, k3.y, s);
    }

    // softmax across the 32 lanes (= 32 keys)
    const float m = warp_max(s);
    const float e = __expf(s - m);
    const float denom = warp_sum(e);
    const float a = e / denom;

    // output phase: lane = dim pair, V read directly from global (L2)
    const __half* vb = V + ((size_t)rowbase << 9) + h * DK + lane * 2;
    float o0 = 0.f, o1 = 0.f;
    #pragma unroll
    for (int k = 0; k < KNN; ++k) {
        const float ak = __shfl_sync(0xffffffffu, a, k);
        const float2 vv = __half22float2(
            *(const __half2*)(vb + ((size_t)srows[k] << 9)));
        o0 = fmaf(ak, vv.x, o0);
        o1 = fmaf(ak, vv.y, o1);
    }
    ((__half2*)(oh + qbase))[lane] = __floats2half2_rn(o0, o1);
}

// ---------------- launch ---------------------------------------------------------
extern "C" void kernel_launch(void* const* d_in, const int* in_sizes, int n_in,
                              void* d_out, int out_size)
{
    const float* x    = (const float*)d_in[0];
    const int*   idx  = (const int*)  d_in[1];
    const float* Wq   = (const float*)d_in[2];
    const float* Wk   = (const float*)d_in[3];
    const float* Wv   = (const float*)d_in[4];
    const float* Wout = (const float*)d_in[5];
    const float* bout = (const float*)d_in[6];
    float* out = (float*)d_out;

    static __half *gQ = nullptr, *gK, *gV, *xh, *ah, *wh;
    if (!gQ) {
        cudaGetSymbolAddress((void**)&gQ, g_Q);
        cudaGetSymbolAddress((void**)&gK, g_K);
        cudaGetSymbolAddress((void**)&gV, g_V);
        cudaGetSymbolAddress((void**)&xh, g_xh);
        cudaGetSymbolAddress((void**)&ah, g_ah);
        cudaGetSymbolAddress((void**)&wh, g_wh);
        cudaFuncSetAttribute((const void*)gemm_f16<1, 1>,
                             cudaFuncAttributeMaxDynamicSharedMemorySize, GEMM_SMEM);
        cudaFuncSetAttribute((const void*)gemm_f16<0, 0>,
                             cudaFuncAttributeMaxDynamicSharedMemorySize, GEMM_SMEM);
        cudaFuncSetAttribute((const void*)attn_kernel,
                             cudaFuncAttributeMaxDynamicSharedMemorySize, ATT_SMEM);
    }

    // conversions
    cvt_h<<<NX / 1024, 256>>>(x, xh);
    cvt_w<<<1024, 256>>>(Wq, Wk, Wv, Wout, wh);

    // fused Q,K,V projections -> fp16; LN fused for Q (x1/8) and K
    gemm_f16<1, 1><<<dim3(12, 64), 256, GEMM_SMEM>>>(xh, wh, gQ, gK, gV, nullptr);

    // attention: K staged in smem, V from L2
    attn_kernel<<<MROWS, 256, ATT_SMEM>>>(gQ, gK, gV, idx, ah);

    // output projection + bias -> fp32 d_out
    gemm_f16<0, 0><<<dim3(4, 64), 256, GEMM_SMEM>>>(ah, wh + 3 * (size_t)NW,
                                                    out, out, out, bout);
}

// round 13
// speedup vs baseline: 4.3914x; 1.0890x over previous
#include <cuda_runtime.h>
#include <cuda_fp16.h>
#include <cstdint>

// Problem constants
#define BATCH 2
#define SEQN  8192
#define DMODEL 512
#define HEADS 8
#define DK 64
#define KNN 32
#define MROWS (BATCH*SEQN)   // 16384
#define LN_EPS 1e-5f
#define NW (DMODEL*DMODEL)   // 262144
#define NX (MROWS*DMODEL)    // 8388608

// ---------------- scratch (device globals; no allocation allowed) -------------
__device__ __align__(128) __half g_Q[NX];
__device__ __align__(128) __half g_K[NX];
__device__ __align__(128) __half g_V[NX];
__device__ __align__(128) __half g_xh[NX];        // x in fp16
__device__ __align__(128) __half g_ah[NX];        // attention out in fp16
__device__ __align__(128) __half g_wh[4 * NW];    // weights fp16

// ---------------- small helpers -------------------------------------------------
__device__ __forceinline__ uint32_t smem_u32(const void* p) {
    uint32_t a;
    asm("{ .reg .u64 t; cvta.to.shared.u64 t, %1; cvt.u32.u64 %0, t; }"
        : "=r"(a) : "l"(p));
    return a;
}
__device__ __forceinline__ void ldsm_x4(uint32_t (&r)[4], uint32_t addr) {
    asm volatile("ldmatrix.sync.aligned.m8n8.x4.shared.b16 {%0,%1,%2,%3}, [%4];"
                 : "=r"(r[0]), "=r"(r[1]), "=r"(r[2]), "=r"(r[3]) : "r"(addr));
}
__device__ __forceinline__ void mma16816(float (&c)[4], const uint32_t (&a)[4],
                                         const uint32_t b0, const uint32_t b1) {
    asm volatile("mma.sync.aligned.m16n8k16.row.col.f32.f16.f16.f32 "
                 "{%0,%1,%2,%3}, {%4,%5,%6,%7}, {%8,%9}, {%0,%1,%2,%3};"
                 : "+f"(c[0]), "+f"(c[1]), "+f"(c[2]), "+f"(c[3])
                 : "r"(a[0]), "r"(a[1]), "r"(a[2]), "r"(a[3]), "r"(b0), "r"(b1));
}
__device__ __forceinline__ void cp16(uint32_t saddr, const void* gaddr) {
    asm volatile("cp.async.cg.shared.global [%0], [%1], 16;"
                 :: "r"(saddr), "l"(gaddr) : "memory");
}
#define CP_COMMIT() asm volatile("cp.async.commit_group;" ::: "memory")
#define CP_WAIT1()  asm volatile("cp.async.wait_group 1;" ::: "memory")
#define CP_WAIT0()  asm volatile("cp.async.wait_group 0;" ::: "memory")

__device__ __forceinline__ float warp_sum(float v) {
    v += __shfl_xor_sync(0xffffffffu, v, 16);
    v += __shfl_xor_sync(0xffffffffu, v, 8);
    v += __shfl_xor_sync(0xffffffffu, v, 4);
    v += __shfl_xor_sync(0xffffffffu, v, 2);
    v += __shfl_xor_sync(0xffffffffu, v, 1);
    return v;
}
__device__ __forceinline__ float warp_max(float v) {
    v = fmaxf(v, __shfl_xor_sync(0xffffffffu, v, 16));
    v = fmaxf(v, __shfl_xor_sync(0xffffffffu, v, 8));
    v = fmaxf(v, __shfl_xor_sync(0xffffffffu, v, 4));
    v = fmaxf(v, __shfl_xor_sync(0xffffffffu, v, 2));
    v = fmaxf(v, __shfl_xor_sync(0xffffffffu, v, 1));
    return v;
}

// ---------------- GEMM: C_t = A(16384x512,fp16) * W_t^T (single fp16 W) ---------
// CTA tile 256(M) x 128(N), BK=64 (half the barriers of BK=32), 8 warps (4m x 2n),
// warp tile 64x64, 3-stage cp.async. OUT_HALF: fp16 vs fp32 output.
// DO_LN: fused per-64-col LayerNorm on tmat 0 (x1/8) and tmat 1.
#define BKC 64
#define NCH (DMODEL / BKC)     // 8
#define PITCH 72               // fp16/row (144B; 144 mod 128 = 16 -> ldsm conflict-free)
#define TILE_A_B (256 * PITCH * 2)      // 36864 B
#define TILE_B_B (128 * PITCH * 2)      // 18432 B
#define STAGE_B (TILE_A_B + TILE_B_B)   // 55296 B
#define NSTAGE 3
#define GEMM_SMEM (NSTAGE * STAGE_B)    // 165888 B

template <int OUT_HALF, int DO_LN>
__global__ __launch_bounds__(256, 1)
void gemm_f16(const __half* __restrict__ A, const __half* __restrict__ Wh,
              void* __restrict__ C0, void* __restrict__ C1, void* __restrict__ C2,
              const float* __restrict__ bias)
{
    extern __shared__ char smem[];
    const uint32_t sbase = smem_u32(smem);
    const int tid  = threadIdx.x;
    const int wid  = tid >> 5;
    const int lane = tid & 31;

    const int tmat = blockIdx.x >> 2;
    const int bnn  = (blockIdx.x & 3) * 128;
    const int bm   = blockIdx.y * 256;
    const int warp_m = wid & 3;
    const int warp_n = wid >> 2;

    const __half* Bh = Wh + (size_t)tmat * NW;
    void* C = (tmat == 0) ? C0 : (tmat == 1) ? C1 : C2;

    const int lr = tid >> 3;             // 0..31
    const int lc = tid & 7;              // 16B chunk (8 per 128B row)

    auto load_stage = [&](int c, int buf) {
        const uint32_t s0 = sbase + buf * STAGE_B;
        const int kc = c * BKC;
        #pragma unroll
        for (int p = 0; p < 8; ++p) {    // A: 256 rows
            const int r = lr + p * 32;
            cp16(s0 + (uint32_t)(r * (PITCH * 2) + lc * 16),
                 A + (size_t)(bm + r) * DMODEL + kc + lc * 8);
        }
        #pragma unroll
        for (int p = 0; p < 4; ++p) {    // B: 128 rows
            const int r = lr + p * 32;
            cp16(s0 + TILE_A_B + (uint32_t)(r * (PITCH * 2) + lc * 16),
                 Bh + (size_t)(bnn + r) * DMODEL + kc + lc * 8);
        }
        CP_COMMIT();
    };

    float acc[4][8][4];
    #pragma unroll
    for (int i = 0; i < 4; i++)
        #pragma unroll
        for (int j = 0; j < 8; j++)
            #pragma unroll
            for (int r = 0; r < 4; r++) acc[i][j][r] = 0.f;

    load_stage(0, 0);
    load_stage(1, 1);

    const int aRow  = lane & 15;
    const int aColB = (lane >> 4) * 8;
    const int quad  = lane >> 3;
    const int bRowL = (quad >> 1) * 8 + (lane & 7);
    const int bColB = (quad & 1) * 8;

    #pragma unroll 1
    for (int c = 0; c < NCH; ++c) {
        const int buf = c % NSTAGE;
        if (c + 1 < NCH) CP_WAIT1(); else CP_WAIT0();
        __syncthreads();
        if (c + 2 < NCH) load_stage(c + 2, (c + 2) % NSTAGE);

        const uint32_t sA  = sbase + buf * STAGE_B;
        const uint32_t sBh = sA + TILE_A_B;

        #pragma unroll
        for (int ks = 0; ks < 4; ++ks) {    // 4 k16 steps per 64-col chunk
            uint32_t af[4][4];
            uint32_t bfr[8][2];
            #pragma unroll
            for (int i = 0; i < 4; ++i) {
                const uint32_t ao = (uint32_t)((warp_m * 64 + i * 16 + aRow) * PITCH
                                               + ks * 16 + aColB) * 2;
                ldsm_x4(af[i], sA + ao);
            }
            #pragma unroll
            for (int p = 0; p < 4; ++p) {
                const uint32_t bo = (uint32_t)((warp_n * 64 + p * 16 + bRowL) * PITCH
                                               + ks * 16 + bColB) * 2;
                uint32_t r0[4];
                ldsm_x4(r0, sBh + bo);
                bfr[2*p][0]   = r0[0]; bfr[2*p][1]   = r0[1];
                bfr[2*p+1][0] = r0[2]; bfr[2*p+1][1] = r0[3];
            }
            #pragma unroll
            for (int i = 0; i < 4; ++i)
                #pragma unroll
                for (int j = 0; j < 8; ++j)
                    mma16816(acc[i][j], af[i], bfr[j][0], bfr[j][1]);
        }
    }

    // fused LayerNorm over the 64-col head group (warp tile N == head group).
    if (DO_LN && tmat <= 1) {
        const float qscale = (tmat == 0) ? 0.125f : 1.0f;
        #pragma unroll
        for (int i = 0; i < 4; ++i) {
            #pragma unroll
            for (int hf = 0; hf < 2; ++hf) {
                float s = 0.f, s2 = 0.f;
                #pragma unroll
                for (int j = 0; j < 8; ++j) {
                    const float c0 = acc[i][j][hf * 2], c1 = acc[i][j][hf * 2 + 1];
                    s += c0 + c1;
                    s2 += c0 * c0 + c1 * c1;
                }
                s  += __shfl_xor_sync(0xffffffffu, s, 1);
                s  += __shfl_xor_sync(0xffffffffu, s, 2);
                s2 += __shfl_xor_sync(0xffffffffu, s2, 1);
                s2 += __shfl_xor_sync(0xffffffffu, s2, 2);
                const float mean = s * (1.f / 64.f);
                const float var  = s2 * (1.f / 64.f) - mean * mean;
                const float rr   = rsqrtf(var + LN_EPS) * qscale;
                #pragma unroll
                for (int j = 0; j < 8; ++j) {
                    acc[i][j][hf * 2]     = (acc[i][j][hf * 2]     - mean) * rr;
                    acc[i][j][hf * 2 + 1] = (acc[i][j][hf * 2 + 1] - mean) * rr;
                }
            }
        }
    }

    // epilogue
    const int mBase = bm + warp_m * 64 + (lane >> 2);
    const int nBase = bnn + warp_n * 64 + (lane & 3) * 2;
    #pragma unroll
    for (int i = 0; i < 4; ++i) {
        #pragma unroll
        for (int j = 0; j < 8; ++j) {
            const int row = mBase + i * 16;
            const int col = nBase + j * 8;
            float2 v0 = make_float2(acc[i][j][0], acc[i][j][1]);
            float2 v1 = make_float2(acc[i][j][2], acc[i][j][3]);
            if (bias) {
                const float b0 = bias[col], b1 = bias[col + 1];
                v0.x += b0; v0.y += b1; v1.x += b0; v1.y += b1;
            }
            if (OUT_HALF) {
                __half* Ch = (__half*)C;
                *(__half2*)(Ch + (size_t)row * DMODEL + col) =
                    __floats2half2_rn(v0.x, v0.y);
                *(__half2*)(Ch + (size_t)(row + 8) * DMODEL + col) =
                    __floats2half2_rn(v1.x, v1.y);
            } else {
                float* Cf = (float*)C;
                *(float2*)(Cf + (size_t)row * DMODEL + col)       = v0;
                *(float2*)(Cf + (size_t)(row + 8) * DMODEL + col) = v1;
            }
        }
    }
}

// ---------------- fp32 -> fp16 (single) ------------------------------------------
__global__ void cvt_h(const float* __restrict__ s, __half* __restrict__ d)
{
    int i = (blockIdx.x * blockDim.x + threadIdx.x) * 4;
    float4 v = *(const float4*)(s + i);
    __half2* p = (__half2*)(d + i);
    p[0] = __floats2half2_rn(v.x, v.y);
    p[1] = __floats2half2_rn(v.z, v.w);
}

// ---------------- weights fp32 -> fp16 --------------------------------------------
__global__ void cvt_w(const float* __restrict__ w0, const float* __restrict__ w1,
                      const float* __restrict__ w2, const float* __restrict__ w3,
                      __half* __restrict__ hi)
{
    const int seg = blockIdx.x >> 8;
    const float* w = (seg == 0) ? w0 : (seg == 1) ? w1 : (seg == 2) ? w2 : w3;
    int i = ((blockIdx.x & 255) * blockDim.x + threadIdx.x) * 4;
    float4 v = *(const float4*)(w + i);
    __half2* hp = (__half2*)(hi + seg * NW + i);
    hp[0] = __floats2half2_rn(v.x, v.y);
    hp[1] = __floats2half2_rn(v.z, v.w);
}

// ---------------- gather-attention: K staged (swizzled), V from global ----------
// smem: K 32KB | q 1KB | rows 128B  -> 6 blocks/SM
#define ATT_SMEM (32768 + 1024 + 128)

__global__ __launch_bounds__(256)
void attn_kernel(const __half* __restrict__ Q, const __half* __restrict__ Kt,
                 const __half* __restrict__ V, const int* __restrict__ idx,
                 __half* __restrict__ oh)
{
    extern __shared__ char sm[];
    const uint32_t sbase = smem_u32(sm);
    int* srows = (int*)(sm + 32768 + 1024);
    const int bn = blockIdx.x;
    const int b  = bn >> 13;
    const int n  = bn & (SEQN - 1);
    const int tid = threadIdx.x;
    const int rowbase = b * SEQN;
    const int ibase = n * KNN;

    if (tid < KNN) srows[tid] = idx[ibase + tid];

    // stage K (swizzled): 32 rows x 1024 B
    const int lrow = tid >> 6;       // 0..3
    const int lchk = tid & 63;       // 16B chunk in row
    #pragma unroll
    for (int p = 0; p < 8; ++p) {
        const int r = p * 4 + lrow;
        const int row = idx[ibase + r];
        const int schk = lchk ^ (r & 7);       // XOR swizzle within 128B groups
        cp16(sbase + (uint32_t)(r * 1024 + schk * 16),
             Kt + ((size_t)(rowbase + row) << 9) + lchk * 8);
    }
    CP_COMMIT();

    const int h    = tid >> 5;
    const int lane = tid & 31;
    const int qbase = bn * DMODEL + h * DK;
    // Q already LayerNorm'd and pre-scaled by 1/8 in the GEMM epilogue.
    const uint32_t qv = *(const uint32_t*)(Q + qbase + lane * 2);
    *(uint32_t*)(sm + 32768 + h * 128 + lane * 4) = qv;

    CP_WAIT0();
    __syncthreads();

    // score phase: lane = key; 8 x (LDS.128 K swizzled + LDS.128 q broadcast)
    float s = 0.f;
    const char* kbase = sm + lane * 1024;
    const char* qb = sm + 32768 + h * 128;
    const int hx = h * 8;
    const int lx = lane & 7;
    #pragma unroll
    for (int i = 0; i < 8; ++i) {
        const uint4 kc = *(const uint4*)(kbase + ((hx + i) ^ lx) * 16);
        const uint4 qc = *(const uint4*)(qb + i * 16);
        float2 k0 = __half22float2(*(const __half2*)&kc.x);
        float2 k1 = __half22float2(*(const __half2*)&kc.y);
        float2 k2 = __half22float2(*(const __half2*)&kc.z);
        float2 k3 = __half22float2(*(const __half2*)&kc.w);
        float2 q0 = __half22float2(*(const __half2*)&qc.x);
        float2 q1 = __half22float2(*(const __half2*)&qc.y);
        float2 q2 = __half22float2(*(const __half2*)&qc.z);
        float2 q3 = __half22float2(*(const __half2*)&qc.w);
        s = fmaf(q0.x, k0.x, s); s = fmaf(q0.y, k0.y, s);
        s = fmaf(q1.x, k1.x, s); s = fmaf(q1.y, k1.y, s);
        s = fmaf(q2.x, k2.x, s); s = fmaf(q2.y, k2.y, s);
        s = fmaf(q3.x, k3.x, s); s = fmaf(q3.y, k3.y, s);
    }

    // softmax across the 32 lanes (= 32 keys)
    const float m = warp_max(s);
    const float e = __expf(s - m);
    const float denom = warp_sum(e);
    const float a = e / denom;

    // output phase: lane = dim pair, V read directly from global (L2)
    const __half* vb = V + ((size_t)rowbase << 9) + h * DK + lane * 2;
    float o0 = 0.f, o1 = 0.f;
    #pragma unroll
    for (int k = 0; k < KNN; ++k) {
        const float ak = __shfl_sync(0xffffffffu, a, k);
        const float2 vv = __half22float2(
            *(const __half2*)(vb + ((size_t)srows[k] << 9)));
        o0 = fmaf(ak, vv.x, o0);
        o1 = fmaf(ak, vv.y, o1);
    }
    ((__half2*)(oh + qbase))[lane] = __floats2half2_rn(o0, o1);
}

// ---------------- launch ---------------------------------------------------------
extern "C" void kernel_launch(void* const* d_in, const int* in_sizes, int n_in,
                              void* d_out, int out_size)
{
    const float* x    = (const float*)d_in[0];
    const int*   idx  = (const int*)  d_in[1];
    const float* Wq   = (const float*)d_in[2];
    const float* Wk   = (const float*)d_in[3];
    const float* Wv   = (const float*)d_in[4];
    const float* Wout = (const float*)d_in[5];
    const float* bout = (const float*)d_in[6];
    float* out = (float*)d_out;

    static __half *gQ = nullptr, *gK, *gV, *xh, *ah, *wh;
    if (!gQ) {
        cudaGetSymbolAddress((void**)&gQ, g_Q);
        cudaGetSymbolAddress((void**)&gK, g_K);
        cudaGetSymbolAddress((void**)&gV, g_V);
        cudaGetSymbolAddress((void**)&xh, g_xh);
        cudaGetSymbolAddress((void**)&ah, g_ah);
        cudaGetSymbolAddress((void**)&wh, g_wh);
        cudaFuncSetAttribute((const void*)gemm_f16<1, 1>,
                             cudaFuncAttributeMaxDynamicSharedMemorySize, GEMM_SMEM);
        cudaFuncSetAttribute((const void*)gemm_f16<0, 0>,
                             cudaFuncAttributeMaxDynamicSharedMemorySize, GEMM_SMEM);
        cudaFuncSetAttribute((const void*)attn_kernel,
                             cudaFuncAttributeMaxDynamicSharedMemorySize, ATT_SMEM);
    }

    // conversions
    cvt_h<<<NX / 1024, 256>>>(x, xh);
    cvt_w<<<1024, 256>>>(Wq, Wk, Wv, Wout, wh);

    // fused Q,K,V projections -> fp16; LN fused for Q (x1/8) and K
    gemm_f16<1, 1><<<dim3(12, 64), 256, GEMM_SMEM>>>(xh, wh, gQ, gK, gV, nullptr);

    // attention: K staged in smem, V from L2
    attn_kernel<<<MROWS, 256, ATT_SMEM>>>(gQ, gK, gV, idx, ah);

    // output projection + bias -> fp32 d_out
    gemm_f16<0, 0><<<dim3(4, 64), 256, GEMM_SMEM>>>(ah, wh + 3 * (size_t)NW,
                                                    out, out, out, bout);
}

// round 14
// speedup vs baseline: 4.6346x; 1.0554x over previous
#include <cuda_runtime.h>
#include <cuda_fp16.h>
#include <cstdint>

// Problem constants
#define BATCH 2
#define SEQN  8192
#define DMODEL 512
#define HEADS 8
#define DK 64
#define KNN 32
#define MROWS (BATCH*SEQN)   // 16384
#define LN_EPS 1e-5f
#define NW (DMODEL*DMODEL)   // 262144
#define NX (MROWS*DMODEL)    // 8388608

// ---------------- scratch (device globals; no allocation allowed) -------------
__device__ __align__(128) __half g_Q[NX];
__device__ __align__(128) __half g_K[NX];
__device__ __align__(128) __half g_V[NX];
__device__ __align__(128) __half g_xh[NX];        // x in fp16
__device__ __align__(128) __half g_ah[NX];        // attention out in fp16
__device__ __align__(128) __half g_wh[4 * NW];    // weights fp16

// ---------------- small helpers -------------------------------------------------
__device__ __forceinline__ uint32_t smem_u32(const void* p) {
    uint32_t a;
    asm("{ .reg .u64 t; cvta.to.shared.u64 t, %1; cvt.u32.u64 %0, t; }"
        : "=r"(a) : "l"(p));
    return a;
}
__device__ __forceinline__ void ldsm_x4(uint32_t (&r)[4], uint32_t addr) {
    asm volatile("ldmatrix.sync.aligned.m8n8.x4.shared.b16 {%0,%1,%2,%3}, [%4];"
                 : "=r"(r[0]), "=r"(r[1]), "=r"(r[2]), "=r"(r[3]) : "r"(addr));
}
__device__ __forceinline__ void mma16816(float (&c)[4], const uint32_t (&a)[4],
                                         const uint32_t b0, const uint32_t b1) {
    asm volatile("mma.sync.aligned.m16n8k16.row.col.f32.f16.f16.f32 "
                 "{%0,%1,%2,%3}, {%4,%5,%6,%7}, {%8,%9}, {%0,%1,%2,%3};"
                 : "+f"(c[0]), "+f"(c[1]), "+f"(c[2]), "+f"(c[3])
                 : "r"(a[0]), "r"(a[1]), "r"(a[2]), "r"(a[3]), "r"(b0), "r"(b1));
}
__device__ __forceinline__ void cp16(uint32_t saddr, const void* gaddr) {
    asm volatile("cp.async.cg.shared.global [%0], [%1], 16;"
                 :: "r"(saddr), "l"(gaddr) : "memory");
}
#define CP_COMMIT() asm volatile("cp.async.commit_group;" ::: "memory")
#define CP_WAIT1()  asm volatile("cp.async.wait_group 1;" ::: "memory")
#define CP_WAIT0()  asm volatile("cp.async.wait_group 0;" ::: "memory")

__device__ __forceinline__ float warp_sum(float v) {
    v += __shfl_xor_sync(0xffffffffu, v, 16);
    v += __shfl_xor_sync(0xffffffffu, v, 8);
    v += __shfl_xor_sync(0xffffffffu, v, 4);
    v += __shfl_xor_sync(0xffffffffu, v, 2);
    v += __shfl_xor_sync(0xffffffffu, v, 1);
    return v;
}
__device__ __forceinline__ float warp_max(float v) {
    v = fmaxf(v, __shfl_xor_sync(0xffffffffu, v, 16));
    v = fmaxf(v, __shfl_xor_sync(0xffffffffu, v, 8));
    v = fmaxf(v, __shfl_xor_sync(0xffffffffu, v, 4));
    v = fmaxf(v, __shfl_xor_sync(0xffffffffu, v, 2));
    v = fmaxf(v, __shfl_xor_sync(0xffffffffu, v, 1));
    return v;
}

// ---------------- GEMM: C_t = A(16384x512,fp16) * W_t^T (single fp16 W) ---------
// CTA tile 128(M) x 128(N), BK=64, 8 warps (4m x 2n), warp tile 32x64.
// 3-stage cp.async, 110.6 KB smem -> 2 CTAs/SM (prologue/epilogue overlap).
// OUT_HALF: fp16 vs fp32 output. DO_LN: fused 64-col LayerNorm (tmat 0 x1/8, 1).
#define BKC 64
#define NCH (DMODEL / BKC)     // 8
#define PITCH 72               // fp16/row (144B; 144 mod 128 = 16 -> ldsm conflict-free)
#define TILE_A_B (128 * PITCH * 2)      // 18432 B
#define TILE_B_B (128 * PITCH * 2)      // 18432 B
#define STAGE_B (TILE_A_B + TILE_B_B)   // 36864 B
#define NSTAGE 3
#define GEMM_SMEM (NSTAGE * STAGE_B)    // 110592 B

template <int OUT_HALF, int DO_LN>
__global__ __launch_bounds__(256, 2)
void gemm_f16(const __half* __restrict__ A, const __half* __restrict__ Wh,
              void* __restrict__ C0, void* __restrict__ C1, void* __restrict__ C2,
              const float* __restrict__ bias)
{
    extern __shared__ char smem[];
    const uint32_t sbase = smem_u32(smem);
    const int tid  = threadIdx.x;
    const int wid  = tid >> 5;
    const int lane = tid & 31;

    const int tmat = blockIdx.x >> 2;
    const int bnn  = (blockIdx.x & 3) * 128;
    const int bm   = blockIdx.y * 128;
    const int warp_m = wid & 3;          // 0..3 (32 rows each)
    const int warp_n = wid >> 2;         // 0..1 (64 cols each)

    const __half* Bh = Wh + (size_t)tmat * NW;
    void* C = (tmat == 0) ? C0 : (tmat == 1) ? C1 : C2;

    const int lr = tid >> 3;             // 0..31
    const int lc = tid & 7;              // 16B chunk (8 per 128B row)

    auto load_stage = [&](int c, int buf) {
        const uint32_t s0 = sbase + buf * STAGE_B;
        const int kc = c * BKC;
        #pragma unroll
        for (int p = 0; p < 4; ++p) {    // A: 128 rows
            const int r = lr + p * 32;
            cp16(s0 + (uint32_t)(r * (PITCH * 2) + lc * 16),
                 A + (size_t)(bm + r) * DMODEL + kc + lc * 8);
        }
        #pragma unroll
        for (int p = 0; p < 4; ++p) {    // B: 128 rows
            const int r = lr + p * 32;
            cp16(s0 + TILE_A_B + (uint32_t)(r * (PITCH * 2) + lc * 16),
                 Bh + (size_t)(bnn + r) * DMODEL + kc + lc * 8);
        }
        CP_COMMIT();
    };

    float acc[2][8][4];
    #pragma unroll
    for (int i = 0; i < 2; i++)
        #pragma unroll
        for (int j = 0; j < 8; j++)
            #pragma unroll
            for (int r = 0; r < 4; r++) acc[i][j][r] = 0.f;

    load_stage(0, 0);
    load_stage(1, 1);

    const int aRow  = lane & 15;
    const int aColB = (lane >> 4) * 8;
    const int quad  = lane >> 3;
    const int bRowL = (quad >> 1) * 8 + (lane & 7);
    const int bColB = (quad & 1) * 8;

    #pragma unroll 1
    for (int c = 0; c < NCH; ++c) {
        const int buf = c % NSTAGE;
        if (c + 1 < NCH) CP_WAIT1(); else CP_WAIT0();
        __syncthreads();
        if (c + 2 < NCH) load_stage(c + 2, (c + 2) % NSTAGE);

        const uint32_t sA  = sbase + buf * STAGE_B;
        const uint32_t sBh = sA + TILE_A_B;

        #pragma unroll
        for (int ks = 0; ks < 4; ++ks) {    // 4 k16 steps per 64-col chunk
            uint32_t af[2][4];
            uint32_t bfr[8][2];
            #pragma unroll
            for (int i = 0; i < 2; ++i) {
                const uint32_t ao = (uint32_t)((warp_m * 32 + i * 16 + aRow) * PITCH
                                               + ks * 16 + aColB) * 2;
                ldsm_x4(af[i], sA + ao);
            }
            #pragma unroll
            for (int p = 0; p < 4; ++p) {
                const uint32_t bo = (uint32_t)((warp_n * 64 + p * 16 + bRowL) * PITCH
                                               + ks * 16 + bColB) * 2;
                uint32_t r0[4];
                ldsm_x4(r0, sBh + bo);
                bfr[2*p][0]   = r0[0]; bfr[2*p][1]   = r0[1];
                bfr[2*p+1][0] = r0[2]; bfr[2*p+1][1] = r0[3];
            }
            #pragma unroll
            for (int i = 0; i < 2; ++i)
                #pragma unroll
                for (int j = 0; j < 8; ++j)
                    mma16816(acc[i][j], af[i], bfr[j][0], bfr[j][1]);
        }
    }

    // fused LayerNorm over the 64-col head group (warp tile N == head group).
    if (DO_LN && tmat <= 1) {
        const float qscale = (tmat == 0) ? 0.125f : 1.0f;
        #pragma unroll
        for (int i = 0; i < 2; ++i) {
            #pragma unroll
            for (int hf = 0; hf < 2; ++hf) {
                float s = 0.f, s2 = 0.f;
                #pragma unroll
                for (int j = 0; j < 8; ++j) {
                    const float c0 = acc[i][j][hf * 2], c1 = acc[i][j][hf * 2 + 1];
                    s += c0 + c1;
                    s2 += c0 * c0 + c1 * c1;
                }
                s  += __shfl_xor_sync(0xffffffffu, s, 1);
                s  += __shfl_xor_sync(0xffffffffu, s, 2);
                s2 += __shfl_xor_sync(0xffffffffu, s2, 1);
                s2 += __shfl_xor_sync(0xffffffffu, s2, 2);
                const float mean = s * (1.f / 64.f);
                const float var  = s2 * (1.f / 64.f) - mean * mean;
                const float rr   = rsqrtf(var + LN_EPS) * qscale;
                #pragma unroll
                for (int j = 0; j < 8; ++j) {
                    acc[i][j][hf * 2]     = (acc[i][j][hf * 2]     - mean) * rr;
                    acc[i][j][hf * 2 + 1] = (acc[i][j][hf * 2 + 1] - mean) * rr;
                }
            }
        }
    }

    // epilogue
    const int mBase = bm + warp_m * 32 + (lane >> 2);
    const int nBase = bnn + warp_n * 64 + (lane & 3) * 2;
    #pragma unroll
    for (int i = 0; i < 2; ++i) {
        #pragma unroll
        for (int j = 0; j < 8; ++j) {
            const int row = mBase + i * 16;
            const int col = nBase + j * 8;
            float2 v0 = make_float2(acc[i][j][0], acc[i][j][1]);
            float2 v1 = make_float2(acc[i][j][2], acc[i][j][3]);
            if (bias) {
                const float b0 = bias[col], b1 = bias[col + 1];
                v0.x += b0; v0.y += b1; v1.x += b0; v1.y += b1;
            }
            if (OUT_HALF) {
                __half* Ch = (__half*)C;
                *(__half2*)(Ch + (size_t)row * DMODEL + col) =
                    __floats2half2_rn(v0.x, v0.y);
                *(__half2*)(Ch + (size_t)(row + 8) * DMODEL + col) =
                    __floats2half2_rn(v1.x, v1.y);
            } else {
                float* Cf = (float*)C;
                *(float2*)(Cf + (size_t)row * DMODEL + col)       = v0;
                *(float2*)(Cf + (size_t)(row + 8) * DMODEL + col) = v1;
            }
        }
    }
}

// ---------------- fp32 -> fp16 (single) ------------------------------------------
__global__ void cvt_h(const float* __restrict__ s, __half* __restrict__ d)
{
    int i = (blockIdx.x * blockDim.x + threadIdx.x) * 4;
    float4 v = *(const float4*)(s + i);
    __half2* p = (__half2*)(d + i);
    p[0] = __floats2half2_rn(v.x, v.y);
    p[1] = __floats2half2_rn(v.z, v.w);
}

// ---------------- weights fp32 -> fp16 --------------------------------------------
__global__ void cvt_w(const float* __restrict__ w0, const float* __restrict__ w1,
                      const float* __restrict__ w2, const float* __restrict__ w3,
                      __half* __restrict__ hi)
{
    const int seg = blockIdx.x >> 8;
    const float* w = (seg == 0) ? w0 : (seg == 1) ? w1 : (seg == 2) ? w2 : w3;
    int i = ((blockIdx.x & 255) * blockDim.x + threadIdx.x) * 4;
    float4 v = *(const float4*)(w + i);
    __half2* hp = (__half2*)(hi + seg * NW + i);
    hp[0] = __floats2half2_rn(v.x, v.y);
    hp[1] = __floats2half2_rn(v.z, v.w);
}

// ---------------- gather-attention: K staged (swizzled), V from global ----------
// smem: K 32KB | q 1KB | rows 128B  -> 6 blocks/SM
#define ATT_SMEM (32768 + 1024 + 128)

__global__ __launch_bounds__(256)
void attn_kernel(const __half* __restrict__ Q, const __half* __restrict__ Kt,
                 const __half* __restrict__ V, const int* __restrict__ idx,
                 __half* __restrict__ oh)
{
    extern __shared__ char sm[];
    const uint32_t sbase = smem_u32(sm);
    int* srows = (int*)(sm + 32768 + 1024);
    const int bn = blockIdx.x;
    const int b  = bn >> 13;
    const int n  = bn & (SEQN - 1);
    const int tid = threadIdx.x;
    const int rowbase = b * SEQN;
    const int ibase = n * KNN;

    if (tid < KNN) srows[tid] = idx[ibase + tid];

    // stage K (swizzled): 32 rows x 1024 B
    const int lrow = tid >> 6;       // 0..3
    const int lchk = tid & 63;       // 16B chunk in row
    #pragma unroll
    for (int p = 0; p < 8; ++p) {
        const int r = p * 4 + lrow;
        const int row = idx[ibase + r];
        const int schk = lchk ^ (r & 7);       // XOR swizzle within 128B groups
        cp16(sbase + (uint32_t)(r * 1024 + schk * 16),
             Kt + ((size_t)(rowbase + row) << 9) + lchk * 8);
    }
    CP_COMMIT();

    const int h    = tid >> 5;
    const int lane = tid & 31;
    const int qbase = bn * DMODEL + h * DK;
    // Q already LayerNorm'd and pre-scaled by 1/8 in the GEMM epilogue.
    const uint32_t qv = *(const uint32_t*)(Q + qbase + lane * 2);
    *(uint32_t*)(sm + 32768 + h * 128 + lane * 4) = qv;

    CP_WAIT0();
    __syncthreads();

    // score phase: lane = key; 8 x (LDS.128 K swizzled + LDS.128 q broadcast)
    float s = 0.f;
    const char* kbase = sm + lane * 1024;
    const char* qb = sm + 32768 + h * 128;
    const int hx = h * 8;
    const int lx = lane & 7;
    #pragma unroll
    for (int i = 0; i < 8; ++i) {
        const uint4 kc = *(const uint4*)(kbase + ((hx + i) ^ lx) * 16);
        const uint4 qc = *(const uint4*)(qb + i * 16);
        float2 k0 = __half22float2(*(const __half2*)&kc.x);
        float2 k1 = __half22float2(*(const __half2*)&kc.y);
        float2 k2 = __half22float2(*(const __half2*)&kc.z);
        float2 k3 = __half22float2(*(const __half2*)&kc.w);
        float2 q0 = __half22float2(*(const __half2*)&qc.x);
        float2 q1 = __half22float2(*(const __half2*)&qc.y);
        float2 q2 = __half22float2(*(const __half2*)&qc.z);
        float2 q3 = __half22float2(*(const __half2*)&qc.w);
        s = fmaf(q0.x, k0.x, s); s = fmaf(q0.y, k0.y, s);
        s = fmaf(q1.x, k1.x, s); s = fmaf(q1.y, k1.y, s);
        s = fmaf(q2.x, k2.x, s); s = fmaf(q2.y, k2.y, s);
        s = fmaf(q3.x, k3.x, s); s = fmaf(q3.y, k3.y, s);
    }

    // softmax across the 32 lanes (= 32 keys)
    const float m = warp_max(s);
    const float e = __expf(s - m);
    const float denom = warp_sum(e);
    const float a = e / denom;

    // output phase: lane = dim pair, V read directly from global (L2)
    const __half* vb = V + ((size_t)rowbase << 9) + h * DK + lane * 2;
    float o0 = 0.f, o1 = 0.f;
    #pragma unroll
    for (int k = 0; k < KNN; ++k) {
        const float ak = __shfl_sync(0xffffffffu, a, k);
        const float2 vv = __half22float2(
            *(const __half2*)(vb + ((size_t)srows[k] << 9)));
        o0 = fmaf(ak, vv.x, o0);
        o1 = fmaf(ak, vv.y, o1);
    }
    ((__half2*)(oh + qbase))[lane] = __floats2half2_rn(o0, o1);
}

// ---------------- launch ---------------------------------------------------------
extern "C" void kernel_launch(void* const* d_in, const int* in_sizes, int n_in,
                              void* d_out, int out_size)
{
    const float* x    = (const float*)d_in[0];
    const int*   idx  = (const int*)  d_in[1];
    const float* Wq   = (const float*)d_in[2];
    const float* Wk   = (const float*)d_in[3];
    const float* Wv   = (const float*)d_in[4];
    const float* Wout = (const float*)d_in[5];
    const float* bout = (const float*)d_in[6];
    float* out = (float*)d_out;

    static __half *gQ = nullptr, *gK, *gV, *xh, *ah, *wh;
    if (!gQ) {
        cudaGetSymbolAddress((void**)&gQ, g_Q);
        cudaGetSymbolAddress((void**)&gK, g_K);
        cudaGetSymbolAddress((void**)&gV, g_V);
        cudaGetSymbolAddress((void**)&xh, g_xh);
        cudaGetSymbolAddress((void**)&ah, g_ah);
        cudaGetSymbolAddress((void**)&wh, g_wh);
        cudaFuncSetAttribute((const void*)gemm_f16<1, 1>,
                             cudaFuncAttributeMaxDynamicSharedMemorySize, GEMM_SMEM);
        cudaFuncSetAttribute((const void*)gemm_f16<0, 0>,
                             cudaFuncAttributeMaxDynamicSharedMemorySize, GEMM_SMEM);
        cudaFuncSetAttribute((const void*)attn_kernel,
                             cudaFuncAttributeMaxDynamicSharedMemorySize, ATT_SMEM);
    }

    // conversions
    cvt_h<<<NX / 1024, 256>>>(x, xh);
    cvt_w<<<1024, 256>>>(Wq, Wk, Wv, Wout, wh);

    // fused Q,K,V projections -> fp16; LN fused for Q (x1/8) and K
    gemm_f16<1, 1><<<dim3(12, 128), 256, GEMM_SMEM>>>(xh, wh, gQ, gK, gV, nullptr);

    // attention: K staged in smem, V from L2
    attn_kernel<<<MROWS, 256, ATT_SMEM>>>(gQ, gK, gV, idx, ah);

    // output projection + bias -> fp32 d_out
    gemm_f16<0, 0><<<dim3(4, 128), 256, GEMM_SMEM>>>(ah, wh + 3 * (size_t)NW,
                                                     out, out, out, bout);
}